// round 2
// baseline (speedup 1.0000x reference)
#include <cuda_runtime.h>
#include <cuda_bf16.h>
#include <math_constants.h>
#include <cstdint>

// ---------------------------------------------------------------------------
// VN_Resnet_Encoder  —  B=8, N=1024, k=20, H=128, LAYER_NUM=4
// Column layout for all feature maps: col = (b*3 + d)*1024 + n,  P = 24576
// ---------------------------------------------------------------------------

#define B_      8
#define N_      1024
#define KNN_    20
#define H_      128
#define PCOLS   24576          // 8*3*1024
#define EPS_    1e-6f

// ---------------- scratch (static device globals; no allocation) -----------
__device__ float g_H0[256 * PCOLS];   // hidden (2H x P)
__device__ float g_T0[256 * PCOLS];   // d0 / a0
__device__ float g_T1[128 * PCOLS];   // hidden_pre, then net
__device__ float g_T2[128 * PCOLS];   // d1 / a1
__device__ float g_T3[128 * PCOLS];   // dx
__device__ float g_T4[128 * PCOLS];   // x_s
__device__ float g_G [B_ * H_ * 3];   // final pooled (b, c, d)

// ---------------------------------------------------------------------------
// Kernel 1: KNN + graph feature cross + conv_pos (VNLinearLeakyReLU) + mean_k
// one block per (b, n); 128 threads; thread = output channel h
// ---------------------------------------------------------------------------
__global__ __launch_bounds__(128)
void knn_conv_kernel(const float* __restrict__ x,     // (B,1,N,3)
                     const float* __restrict__ Wf,    // (H,3)
                     const float* __restrict__ Wd,    // (H,3)
                     float* __restrict__ Hpre)        // (H, PCOLS)
{
    __shared__ float px[N_], py[N_], pz[N_];
    __shared__ float sc[N_];
    __shared__ int   nb[KNN_];
    __shared__ float wmax[4];
    __shared__ int   warg[4];

    const int b = blockIdx.x >> 10;
    const int n = blockIdx.x & 1023;
    const float* xb = x + (size_t)b * N_ * 3;

    for (int i = threadIdx.x; i < N_; i += 128) {
        px[i] = xb[i * 3 + 0];
        py[i] = xb[i * 3 + 1];
        pz[i] = xb[i * 3 + 2];
    }
    __syncthreads();

    const float cx = px[n], cy = py[n], cz = pz[n];

    for (int i = threadIdx.x; i < N_; i += 128) {
        float dx = px[i] - cx, dy = py[i] - cy, dz = pz[i] - cz;
        sc[i] = -(dx * dx + dy * dy + dz * dz);   // neg squared distance
    }
    __syncthreads();

    const int lane = threadIdx.x & 31, wrp = threadIdx.x >> 5;

    // 20 serial argmax passes (ties -> lower index, matching lax.top_k)
    for (int kk = 0; kk < KNN_; kk++) {
        float best = -CUDART_INF_F;
        int   bi   = 1 << 30;
        for (int i = threadIdx.x; i < N_; i += 128) {
            float s = sc[i];
            if (s > best || (s == best && i < bi)) { best = s; bi = i; }
        }
        #pragma unroll
        for (int o = 16; o; o >>= 1) {
            float ob = __shfl_down_sync(0xffffffffu, best, o);
            int   oi = __shfl_down_sync(0xffffffffu, bi,   o);
            if (ob > best || (ob == best && oi < bi)) { best = ob; bi = oi; }
        }
        if (lane == 0) { wmax[wrp] = best; warg[wrp] = bi; }
        __syncthreads();
        if (threadIdx.x == 0) {
            float bb = wmax[0]; int ii = warg[0];
            #pragma unroll
            for (int w = 1; w < 4; w++)
                if (wmax[w] > bb || (wmax[w] == bb && warg[w] < ii)) { bb = wmax[w]; ii = warg[w]; }
            nb[kk] = ii;
            sc[ii] = -CUDART_INF_F;
        }
        __syncthreads();
    }

    // conv_pos: p = Wf @ F, d = Wd @ F with F rows {neigh-center, center, cross}
    const int h = threadIdx.x;
    const float wf0 = Wf[h * 3 + 0], wf1 = Wf[h * 3 + 1], wf2 = Wf[h * 3 + 2];
    const float wd0 = Wd[h * 3 + 0], wd1 = Wd[h * 3 + 1], wd2 = Wd[h * 3 + 2];

    float a0 = 0.f, a1 = 0.f, a2 = 0.f;
    #pragma unroll 4
    for (int kk = 0; kk < KNN_; kk++) {
        int j = nb[kk];
        float nx = px[j], ny = py[j], nz = pz[j];
        float e0 = nx - cx, e1 = ny - cy, e2 = nz - cz;
        // cross(neigh, center)
        float r0 = ny * cz - nz * cy;
        float r1 = nz * cx - nx * cz;
        float r2 = nx * cy - ny * cx;

        float pd0 = wf0 * e0 + wf1 * cx + wf2 * r0;
        float pd1 = wf0 * e1 + wf1 * cy + wf2 * r1;
        float pd2 = wf0 * e2 + wf1 * cz + wf2 * r2;
        float dd0 = wd0 * e0 + wd1 * cx + wd2 * r0;
        float dd1 = wd0 * e1 + wd1 * cy + wd2 * r1;
        float dd2 = wd0 * e2 + wd1 * cz + wd2 * r2;

        float dot = pd0 * dd0 + pd1 * dd1 + pd2 * dd2;
        float dsq = dd0 * dd0 + dd1 * dd1 + dd2 * dd2;
        float f   = dot / (dsq + EPS_);
        bool  pos = (dot >= 0.f);
        a0 += 0.2f * pd0 + 0.8f * (pos ? pd0 : pd0 - f * dd0);
        a1 += 0.2f * pd1 + 0.8f * (pos ? pd1 : pd1 - f * dd1);
        a2 += 0.2f * pd2 + 0.8f * (pos ? pd2 : pd2 - f * dd2);
    }

    size_t base = (size_t)h * PCOLS + (size_t)b * 3 * N_ + n;
    Hpre[base         ] = a0 * (1.0f / KNN_);
    Hpre[base + N_    ] = a1 * (1.0f / KNN_);
    Hpre[base + 2 * N_] = a2 * (1.0f / KNN_);
}

// ---------------------------------------------------------------------------
// Kernel 2: SGEMM  C(MxP) = W(MxK) @ X(KxP)   BM=BP=128, BK=16, 256 threads
// ---------------------------------------------------------------------------
__global__ __launch_bounds__(256)
void sgemm_kernel(const float* __restrict__ W, const float* __restrict__ X,
                  float* __restrict__ C, int M, int K)
{
    __shared__ float Ws[16][128];
    __shared__ float Xs[16][132];

    const int t    = threadIdx.x;
    const int rowg = (t >> 4) * 8;     // 0..120
    const int colg = (t & 15) * 8;     // 0..120
    const int m0   = blockIdx.y * 128;
    const int p0   = blockIdx.x * 128;

    float acc[8][8];
    #pragma unroll
    for (int i = 0; i < 8; i++)
        #pragma unroll
        for (int j = 0; j < 8; j++) acc[i][j] = 0.f;

    for (int k0 = 0; k0 < K; k0 += 16) {
        #pragma unroll
        for (int i = 0; i < 8; i++) {
            int idx = t + i * 256;            // 0..2047
            int r = idx >> 4, kk = idx & 15;
            Ws[kk][r] = W[(size_t)(m0 + r) * K + k0 + kk];
        }
        #pragma unroll
        for (int i = 0; i < 8; i++) {
            int idx = t + i * 256;
            int kk = idx >> 7, c = idx & 127;
            Xs[kk][c] = X[(size_t)(k0 + kk) * PCOLS + p0 + c];
        }
        __syncthreads();

        #pragma unroll
        for (int kk = 0; kk < 16; kk++) {
            float ra[8], rb[8];
            #pragma unroll
            for (int i = 0; i < 8; i++) ra[i] = Ws[kk][rowg + i];
            #pragma unroll
            for (int j = 0; j < 8; j++) rb[j] = Xs[kk][colg + j];
            #pragma unroll
            for (int i = 0; i < 8; i++)
                #pragma unroll
                for (int j = 0; j < 8; j++)
                    acc[i][j] = fmaf(ra[i], rb[j], acc[i][j]);
        }
        __syncthreads();
    }

    #pragma unroll
    for (int i = 0; i < 8; i++)
        #pragma unroll
        for (int j = 0; j < 8; j++)
            C[(size_t)(m0 + rowg + i) * PCOLS + p0 + colg + j] = acc[i][j];
}

// ---------------------------------------------------------------------------
// Kernel 3: VN leaky-relu.   Pm = pre-activation P, Dm = direction D (in/out)
// out written into Dm.  One thread per (c, b, n); handles all 3 spatial dims.
// ---------------------------------------------------------------------------
__global__ __launch_bounds__(256)
void vn_lrelu_kernel(const float* __restrict__ Pm, float* __restrict__ Dm,
                     int C, float slope)
{
    int idx = blockIdx.x * 256 + threadIdx.x;
    if (idx >= C * B_ * N_) return;
    int c = idx / (B_ * N_);
    int r = idx - c * (B_ * N_);
    int b = r >> 10, n = r & 1023;

    size_t base = (size_t)c * PCOLS + (size_t)b * 3 * N_ + n;
    float p0 = Pm[base], p1 = Pm[base + N_], p2 = Pm[base + 2 * N_];
    float d0 = Dm[base], d1 = Dm[base + N_], d2 = Dm[base + 2 * N_];

    float dot = p0 * d0 + p1 * d1 + p2 * d2;
    float dsq = d0 * d0 + d1 * d1 + d2 * d2;
    float f   = dot / (dsq + EPS_);
    bool  pos = (dot >= 0.f);
    float om  = 1.f - slope;
    Dm[base         ] = slope * p0 + om * (pos ? p0 : p0 - f * d0);
    Dm[base + N_    ] = slope * p1 + om * (pos ? p1 : p1 - f * d1);
    Dm[base + 2 * N_] = slope * p2 + om * (pos ? p2 : p2 - f * d2);
}

// ---------------------------------------------------------------------------
// Kernel 4: h = xs + dx ; pooled = mean_n(h) ; H0[0:128]=h, H0[128:256]=pooled
// (or, on the last block, write pooled -> G).  One block per (c, b, d).
// ---------------------------------------------------------------------------
__global__ __launch_bounds__(256)
void addpool_kernel(const float* __restrict__ Xs, const float* __restrict__ Dx,
                    float* __restrict__ H0, float* __restrict__ G, int last)
{
    __shared__ float red[256];
    const int c  = blockIdx.x / (B_ * 3);
    const int bd = blockIdx.x % (B_ * 3);          // b*3 + d
    const size_t col0 = (size_t)bd * N_;
    const size_t in_b = (size_t)c * PCOLS + col0;

    float sum = 0.f;
    #pragma unroll
    for (int i = 0; i < 4; i++) {
        int n = threadIdx.x + i * 256;
        float h = Xs[in_b + n] + Dx[in_b + n];
        sum += h;
        if (!last) H0[(size_t)c * PCOLS + col0 + n] = h;
    }
    red[threadIdx.x] = sum;
    __syncthreads();
    for (int s = 128; s > 0; s >>= 1) {
        if (threadIdx.x < s) red[threadIdx.x] += red[threadIdx.x + s];
        __syncthreads();
    }
    float pooled = red[0] * (1.f / N_);
    if (!last) {
        #pragma unroll
        for (int i = 0; i < 4; i++) {
            int n = threadIdx.x + i * 256;
            H0[(size_t)(c + 128) * PCOLS + col0 + n] = pooled;
        }
    } else if (threadIdx.x == 0) {
        G[(bd / 3) * (H_ * 3) + c * 3 + (bd % 3)] = pooled;
    }
}

// ---------------------------------------------------------------------------
// Kernel 5: head — act = vn_lrelu(hidden, Wd@hidden, 0.2); out = Wc @ act
// one block per batch, 128 threads (= channel)
// ---------------------------------------------------------------------------
__global__ __launch_bounds__(128)
void head_kernel(const float* __restrict__ G, const float* __restrict__ Wd,
                 const float* __restrict__ Wc, float* __restrict__ out)
{
    __shared__ float hid[H_][3];
    __shared__ float act[H_][3];
    const int b = blockIdx.x, h = threadIdx.x;

    hid[h][0] = G[b * (H_ * 3) + h * 3 + 0];
    hid[h][1] = G[b * (H_ * 3) + h * 3 + 1];
    hid[h][2] = G[b * (H_ * 3) + h * 3 + 2];
    __syncthreads();

    float d0 = 0.f, d1 = 0.f, d2 = 0.f;
    #pragma unroll 8
    for (int c = 0; c < H_; c++) {
        float w = Wd[h * H_ + c];
        d0 = fmaf(w, hid[c][0], d0);
        d1 = fmaf(w, hid[c][1], d1);
        d2 = fmaf(w, hid[c][2], d2);
    }
    float p0 = hid[h][0], p1 = hid[h][1], p2 = hid[h][2];
    float dot = p0 * d0 + p1 * d1 + p2 * d2;
    float dsq = d0 * d0 + d1 * d1 + d2 * d2;
    float f   = dot / (dsq + EPS_);
    bool  pos = (dot >= 0.f);
    act[h][0] = 0.2f * p0 + 0.8f * (pos ? p0 : p0 - f * d0);
    act[h][1] = 0.2f * p1 + 0.8f * (pos ? p1 : p1 - f * d1);
    act[h][2] = 0.2f * p2 + 0.8f * (pos ? p2 : p2 - f * d2);
    __syncthreads();

    float o0 = 0.f, o1 = 0.f, o2 = 0.f;
    #pragma unroll 8
    for (int c = 0; c < H_; c++) {
        float w = Wc[h * H_ + c];
        o0 = fmaf(w, act[c][0], o0);
        o1 = fmaf(w, act[c][1], o1);
        o2 = fmaf(w, act[c][2], o2);
    }
    out[b * (H_ * 3) + h * 3 + 0] = o0;
    out[b * (H_ * 3) + h * 3 + 1] = o1;
    out[b * (H_ * 3) + h * 3 + 2] = o2;
}

// ---------------------------------------------------------------------------
// launcher
// ---------------------------------------------------------------------------
extern "C" void kernel_launch(void* const* d_in, const int* in_sizes, int n_in,
                              void* d_out, int out_size)
{
    const float* x       = (const float*)d_in[0];   // (8,1,1024,3)
    const float* cpWf    = (const float*)d_in[1];   // (128,3)
    const float* cpWd    = (const float*)d_in[2];   // (128,3)
    const float* fcposW  = (const float*)d_in[3];   // (256,128)
    const float* blkWd0  = (const float*)d_in[4];   // (4,256,256)
    const float* blkW0   = (const float*)d_in[5];   // (4,128,256)
    const float* blkWd1  = (const float*)d_in[6];   // (4,128,128)
    const float* blkW1   = (const float*)d_in[7];   // (4,128,128)
    const float* blkWs   = (const float*)d_in[8];   // (4,128,256)
    const float* actWd   = (const float*)d_in[9];   // (128,128)
    const float* fccW    = (const float*)d_in[10];  // (128,128)
    float* out = (float*)d_out;

    float *H0, *T0, *T1, *T2, *T3, *T4, *G;
    cudaGetSymbolAddress((void**)&H0, g_H0);
    cudaGetSymbolAddress((void**)&T0, g_T0);
    cudaGetSymbolAddress((void**)&T1, g_T1);
    cudaGetSymbolAddress((void**)&T2, g_T2);
    cudaGetSymbolAddress((void**)&T3, g_T3);
    cudaGetSymbolAddress((void**)&T4, g_T4);
    cudaGetSymbolAddress((void**)&G,  g_G);

    const int NPB = PCOLS / 128;      // 192 column tiles

    // stage A: knn + feature + conv_pos + mean_k  -> T1 (128 x P)
    knn_conv_kernel<<<B_ * N_, 128>>>(x, cpWf, cpWd, T1);

    // fc_pos: H0 = fc_pos_W (256x128) @ T1
    sgemm_kernel<<<dim3(NPB, 2), 256>>>(fcposW, T1, H0, 256, 128);

    for (int i = 0; i < 4; i++) {
        const float* Wd0 = blkWd0 + (size_t)i * 256 * 256;
        const float* W0  = blkW0  + (size_t)i * 128 * 256;
        const float* Wd1 = blkWd1 + (size_t)i * 128 * 128;
        const float* W1  = blkW1  + (size_t)i * 128 * 128;
        const float* Ws_ = blkWs  + (size_t)i * 128 * 256;

        // d0 = Wd0 @ hidden ; a0 = lrelu(hidden, d0, 0) in-place in T0
        sgemm_kernel<<<dim3(NPB, 2), 256>>>(Wd0, H0, T0, 256, 256);
        vn_lrelu_kernel<<<(256 * B_ * N_) / 256, 256>>>(H0, T0, 256, 0.0f);

        // net = W0 @ a0
        sgemm_kernel<<<dim3(NPB, 1), 256>>>(W0, T0, T1, 128, 256);

        // d1 = Wd1 @ net ; a1 = lrelu(net, d1, 0) in-place in T2
        sgemm_kernel<<<dim3(NPB, 1), 256>>>(Wd1, T1, T2, 128, 128);
        vn_lrelu_kernel<<<(128 * B_ * N_) / 256, 256>>>(T1, T2, 128, 0.0f);

        // dx = W1 @ a1 ; xs = Ws @ hidden
        sgemm_kernel<<<dim3(NPB, 1), 256>>>(W1, T2, T3, 128, 128);
        sgemm_kernel<<<dim3(NPB, 1), 256>>>(Ws_, H0, T4, 128, 256);

        // h = xs + dx ; pool ; concat -> H0 (or G on last block)
        addpool_kernel<<<H_ * B_ * 3, 256>>>(T4, T3, H0, G, (i == 3) ? 1 : 0);
    }

    head_kernel<<<B_, 128>>>(G, actWd, fccW, out);

    (void)in_sizes; (void)n_in; (void)out_size;
}

// round 5
// speedup vs baseline: 1.9146x; 1.9146x over previous
#include <cuda_runtime.h>
#include <math_constants.h>
#include <cstdint>

// ---------------------------------------------------------------------------
// VN_Resnet_Encoder — B=8, N=1024, k=20, H=128, LAYER_NUM=4
// Column layout: col = (b*3 + d)*1024 + n,  P = 24576
// GEMMs via 3xTF32 mma.sync (fp32-accurate), pooled half folded into bias.
// ---------------------------------------------------------------------------

#define B_      8
#define N_      1024
#define KNN_    20
#define H_      128
#define PCOLS   24576
#define EPS_    1e-6f

// ---------------- scratch (static device globals; no allocation) -----------
__device__ float g_H0[256 * PCOLS];   // layer0: full 2H x P; layers>=1: h (H x P) in first half
__device__ float g_T0[256 * PCOLS];   // d0 / a0
__device__ float g_T1[128 * PCOLS];   // knn out, then net
__device__ float g_T2[128 * PCOLS];   // d1 / a1
__device__ float g_T3[128 * PCOLS];   // dx
__device__ float g_T4[128 * PCOLS];   // x_s
__device__ float g_P128[H_ * 24];     // pooled (c, b*3+d)
__device__ float g_bWd0[256 * 24];    // bias for Wd0 @ pooled-half
__device__ float g_bWs [128 * 24];    // bias for Ws  @ pooled-half

// ---------------------------------------------------------------------------
// Kernel 1: KNN + graph feature cross + conv_pos + mean_k
// ---------------------------------------------------------------------------
__global__ __launch_bounds__(128)
void knn_conv_kernel(const float* __restrict__ x,
                     const float* __restrict__ Wf,
                     const float* __restrict__ Wd,
                     float* __restrict__ Hpre)
{
    __shared__ float px[N_], py[N_], pz[N_];
    __shared__ float sc[N_];
    __shared__ int   nb[KNN_];
    __shared__ float wmax[4];
    __shared__ int   warg[4];

    const int b = blockIdx.x >> 10;
    const int n = blockIdx.x & 1023;
    const float* xb = x + (size_t)b * N_ * 3;

    for (int i = threadIdx.x; i < N_; i += 128) {
        px[i] = xb[i * 3 + 0];
        py[i] = xb[i * 3 + 1];
        pz[i] = xb[i * 3 + 2];
    }
    __syncthreads();

    const float cx = px[n], cy = py[n], cz = pz[n];

    for (int i = threadIdx.x; i < N_; i += 128) {
        float dx = px[i] - cx, dy = py[i] - cy, dz = pz[i] - cz;
        sc[i] = -(dx * dx + dy * dy + dz * dz);
    }
    __syncthreads();

    const int lane = threadIdx.x & 31, wrp = threadIdx.x >> 5;

    for (int kk = 0; kk < KNN_; kk++) {
        float best = -CUDART_INF_F;
        int   bi   = 1 << 30;
        for (int i = threadIdx.x; i < N_; i += 128) {
            float s = sc[i];
            if (s > best || (s == best && i < bi)) { best = s; bi = i; }
        }
        #pragma unroll
        for (int o = 16; o; o >>= 1) {
            float ob = __shfl_down_sync(0xffffffffu, best, o);
            int   oi = __shfl_down_sync(0xffffffffu, bi,   o);
            if (ob > best || (ob == best && oi < bi)) { best = ob; bi = oi; }
        }
        if (lane == 0) { wmax[wrp] = best; warg[wrp] = bi; }
        __syncthreads();
        if (threadIdx.x == 0) {
            float bb = wmax[0]; int ii = warg[0];
            #pragma unroll
            for (int w = 1; w < 4; w++)
                if (wmax[w] > bb || (wmax[w] == bb && warg[w] < ii)) { bb = wmax[w]; ii = warg[w]; }
            nb[kk] = ii;
            sc[ii] = -CUDART_INF_F;
        }
        __syncthreads();
    }

    const int h = threadIdx.x;
    const float wf0 = Wf[h * 3 + 0], wf1 = Wf[h * 3 + 1], wf2 = Wf[h * 3 + 2];
    const float wd0 = Wd[h * 3 + 0], wd1 = Wd[h * 3 + 1], wd2 = Wd[h * 3 + 2];

    float a0 = 0.f, a1 = 0.f, a2 = 0.f;
    #pragma unroll 4
    for (int kk = 0; kk < KNN_; kk++) {
        int j = nb[kk];
        float nx = px[j], ny = py[j], nz = pz[j];
        float e0 = nx - cx, e1 = ny - cy, e2 = nz - cz;
        float r0 = ny * cz - nz * cy;
        float r1 = nz * cx - nx * cz;
        float r2 = nx * cy - ny * cx;

        float pd0 = wf0 * e0 + wf1 * cx + wf2 * r0;
        float pd1 = wf0 * e1 + wf1 * cy + wf2 * r1;
        float pd2 = wf0 * e2 + wf1 * cz + wf2 * r2;
        float dd0 = wd0 * e0 + wd1 * cx + wd2 * r0;
        float dd1 = wd0 * e1 + wd1 * cy + wd2 * r1;
        float dd2 = wd0 * e2 + wd1 * cz + wd2 * r2;

        float dot = pd0 * dd0 + pd1 * dd1 + pd2 * dd2;
        float dsq = dd0 * dd0 + dd1 * dd1 + dd2 * dd2;
        float f   = dot / (dsq + EPS_);
        bool  pos = (dot >= 0.f);
        a0 += 0.2f * pd0 + 0.8f * (pos ? pd0 : pd0 - f * dd0);
        a1 += 0.2f * pd1 + 0.8f * (pos ? pd1 : pd1 - f * dd1);
        a2 += 0.2f * pd2 + 0.8f * (pos ? pd2 : pd2 - f * dd2);
    }

    size_t base = (size_t)h * PCOLS + (size_t)b * 3 * N_ + n;
    Hpre[base         ] = a0 * (1.0f / KNN_);
    Hpre[base + N_    ] = a1 * (1.0f / KNN_);
    Hpre[base + 2 * N_] = a2 * (1.0f / KNN_);
}

// ---------------------------------------------------------------------------
// Kernel 2: 3xTF32 tensor-core GEMM.  C(M x PCOLS) = W(M x K, lda) @ X(K x P)
// BM=128, BN=64, BK=16. 8 warps (4 x 2), warp tile 32x32, m16n8k8 mma.
// Optional bias[m][bd] added in epilogue (bd = col >> 10).
// ---------------------------------------------------------------------------
__device__ __forceinline__ uint32_t f2tf32(float f) {
    uint32_t u; asm("cvt.rna.tf32.f32 %0, %1;" : "=r"(u) : "f"(f)); return u;
}

#define MMA_TF32(c0,c1,c2,c3,a0,a1,a2,a3,b0,b1)                              \
    asm volatile("mma.sync.aligned.m16n8k8.row.col.f32.tf32.tf32.f32 "       \
        "{%0,%1,%2,%3},{%4,%5,%6,%7},{%8,%9},{%0,%1,%2,%3};"                 \
        : "+f"(c0),"+f"(c1),"+f"(c2),"+f"(c3)                                \
        : "r"(a0),"r"(a1),"r"(a2),"r"(a3),"r"(b0),"r"(b1))

__global__ __launch_bounds__(256)
void gemm_tf32x3(const float* __restrict__ W, int lda,
                 const float* __restrict__ X, float* __restrict__ C,
                 int K, const float* __restrict__ bias)
{
    __shared__ uint32_t WsH[16][136];
    __shared__ uint32_t WsL[16][136];
    __shared__ uint32_t XsH[16][72];
    __shared__ uint32_t XsL[16][72];
    __shared__ float    bsh[128];

    const int t    = threadIdx.x;
    const int p0   = blockIdx.x * 64;
    const int m0   = blockIdx.y * 128;
    const int warp = t >> 5, lane = t & 31;
    const int wm   = (warp & 3) * 32;
    const int wn   = (warp >> 2) * 32;
    const int g    = lane >> 2, tg = lane & 3;

    if (t < 128) bsh[t] = bias ? bias[(m0 + t) * 24 + (p0 >> 10)] : 0.0f;

    float acc[2][4][4];
    #pragma unroll
    for (int i = 0; i < 2; i++)
        #pragma unroll
        for (int j = 0; j < 4; j++)
            #pragma unroll
            for (int l = 0; l < 4; l++) acc[i][j][l] = 0.f;

    for (int k0 = 0; k0 < K; k0 += 16) {
        // stage W tile (128 x 16) as hi/lo tf32, layout [k][m]
        #pragma unroll
        for (int i = 0; i < 2; i++) {
            int idx = t + i * 256;            // 0..511
            int r   = idx >> 2;               // 0..127
            int c4  = (idx & 3) * 4;          // 0,4,8,12
            float4 v = *(const float4*)(W + (size_t)(m0 + r) * lda + k0 + c4);
            float vv[4] = {v.x, v.y, v.z, v.w};
            #pragma unroll
            for (int j = 0; j < 4; j++) {
                uint32_t hi = f2tf32(vv[j]);
                float lo = vv[j] - __uint_as_float(hi);
                WsH[c4 + j][r] = hi;
                WsL[c4 + j][r] = f2tf32(lo);
            }
        }
        // stage X tile (16 x 64) as hi/lo tf32, layout [k][n]
        {
            int r  = t >> 4;                  // 0..15
            int c4 = (t & 15) * 4;            // 0..60
            float4 v = *(const float4*)(X + (size_t)(k0 + r) * PCOLS + p0 + c4);
            float vv[4] = {v.x, v.y, v.z, v.w};
            #pragma unroll
            for (int j = 0; j < 4; j++) {
                uint32_t hi = f2tf32(vv[j]);
                float lo = vv[j] - __uint_as_float(hi);
                XsH[r][c4 + j] = hi;
                XsL[r][c4 + j] = f2tf32(lo);
            }
        }
        __syncthreads();

        #pragma unroll
        for (int ks = 0; ks < 2; ks++) {
            const int kb = ks * 8;
            uint32_t ah[2][4], al[2][4];
            #pragma unroll
            for (int mt = 0; mt < 2; mt++) {
                int rr = wm + mt * 16 + g;
                ah[mt][0] = WsH[kb + tg    ][rr    ];  al[mt][0] = WsL[kb + tg    ][rr    ];
                ah[mt][1] = WsH[kb + tg    ][rr + 8];  al[mt][1] = WsL[kb + tg    ][rr + 8];
                ah[mt][2] = WsH[kb + tg + 4][rr    ];  al[mt][2] = WsL[kb + tg + 4][rr    ];
                ah[mt][3] = WsH[kb + tg + 4][rr + 8];  al[mt][3] = WsL[kb + tg + 4][rr + 8];
            }
            #pragma unroll
            for (int nt = 0; nt < 4; nt++) {
                int cc = wn + nt * 8 + g;
                uint32_t bh0 = XsH[kb + tg    ][cc], bl0 = XsL[kb + tg    ][cc];
                uint32_t bh1 = XsH[kb + tg + 4][cc], bl1 = XsL[kb + tg + 4][cc];
                #pragma unroll
                for (int mt = 0; mt < 2; mt++) {
                    MMA_TF32(acc[mt][nt][0], acc[mt][nt][1], acc[mt][nt][2], acc[mt][nt][3],
                             al[mt][0], al[mt][1], al[mt][2], al[mt][3], bh0, bh1);
                    MMA_TF32(acc[mt][nt][0], acc[mt][nt][1], acc[mt][nt][2], acc[mt][nt][3],
                             ah[mt][0], ah[mt][1], ah[mt][2], ah[mt][3], bl0, bl1);
                    MMA_TF32(acc[mt][nt][0], acc[mt][nt][1], acc[mt][nt][2], acc[mt][nt][3],
                             ah[mt][0], ah[mt][1], ah[mt][2], ah[mt][3], bh0, bh1);
                }
            }
        }
        __syncthreads();
    }

    #pragma unroll
    for (int mt = 0; mt < 2; mt++) {
        int r0 = wm + mt * 16 + g;
        float b0v = bsh[r0], b1v = bsh[r0 + 8];
        #pragma unroll
        for (int nt = 0; nt < 4; nt++) {
            int col = p0 + wn + nt * 8 + 2 * tg;
            float2 v0 = make_float2(acc[mt][nt][0] + b0v, acc[mt][nt][1] + b0v);
            float2 v1 = make_float2(acc[mt][nt][2] + b1v, acc[mt][nt][3] + b1v);
            *(float2*)(C + (size_t)(m0 + r0    ) * PCOLS + col) = v0;
            *(float2*)(C + (size_t)(m0 + r0 + 8) * PCOLS + col) = v1;
        }
    }
}

// ---------------------------------------------------------------------------
// Kernel 3: VN leaky-relu (float4 over n). p from Pm (c<128 or Pp==null) or
// pooled vector Pp (c>=128). Output overwrites Dm.
// ---------------------------------------------------------------------------
__global__ __launch_bounds__(256)
void vn_lrelu4(const float* __restrict__ Pm, const float* __restrict__ Pp,
               float* __restrict__ Dm, float slope)
{
    int idx = blockIdx.x * 256 + threadIdx.x;       // c * 2048 + r
    int c  = idx >> 11;
    int r  = idx & 2047;
    int b  = r >> 8;
    int n4 = (r & 255) << 2;
    size_t base = (size_t)c * PCOLS + (size_t)b * 3072 + n4;

    float4 d0 = *(const float4*)(Dm + base);
    float4 d1 = *(const float4*)(Dm + base + 1024);
    float4 d2 = *(const float4*)(Dm + base + 2048);
    float4 p0, p1, p2;
    if (Pp != nullptr && c >= 128) {
        float v0 = Pp[(c - 128) * 24 + b * 3 + 0];
        float v1 = Pp[(c - 128) * 24 + b * 3 + 1];
        float v2 = Pp[(c - 128) * 24 + b * 3 + 2];
        p0 = make_float4(v0, v0, v0, v0);
        p1 = make_float4(v1, v1, v1, v1);
        p2 = make_float4(v2, v2, v2, v2);
    } else {
        p0 = *(const float4*)(Pm + base);
        p1 = *(const float4*)(Pm + base + 1024);
        p2 = *(const float4*)(Pm + base + 2048);
    }

    float P0[4] = {p0.x, p0.y, p0.z, p0.w};
    float P1[4] = {p1.x, p1.y, p1.z, p1.w};
    float P2[4] = {p2.x, p2.y, p2.z, p2.w};
    float D0[4] = {d0.x, d0.y, d0.z, d0.w};
    float D1[4] = {d1.x, d1.y, d1.z, d1.w};
    float D2[4] = {d2.x, d2.y, d2.z, d2.w};
    float O0[4], O1[4], O2[4];
    const float om = 1.f - slope;
    #pragma unroll
    for (int j = 0; j < 4; j++) {
        float dot = P0[j] * D0[j] + P1[j] * D1[j] + P2[j] * D2[j];
        float dsq = D0[j] * D0[j] + D1[j] * D1[j] + D2[j] * D2[j];
        float f   = dot / (dsq + EPS_);
        bool  pos = (dot >= 0.f);
        O0[j] = slope * P0[j] + om * (pos ? P0[j] : P0[j] - f * D0[j]);
        O1[j] = slope * P1[j] + om * (pos ? P1[j] : P1[j] - f * D1[j]);
        O2[j] = slope * P2[j] + om * (pos ? P2[j] : P2[j] - f * D2[j]);
    }
    *(float4*)(Dm + base       ) = make_float4(O0[0], O0[1], O0[2], O0[3]);
    *(float4*)(Dm + base + 1024) = make_float4(O1[0], O1[1], O1[2], O1[3]);
    *(float4*)(Dm + base + 2048) = make_float4(O2[0], O2[1], O2[2], O2[3]);
}

// ---------------------------------------------------------------------------
// Kernel 4: h = xs + dx ; write h to Hh (unless last) ; pooled -> P128[c][bd]
// one block per (c, bd); 256 threads x float4
// ---------------------------------------------------------------------------
__global__ __launch_bounds__(256)
void addpool4(const float* __restrict__ Xs, const float* __restrict__ Dx,
              float* __restrict__ Hh, float* __restrict__ P, int last)
{
    __shared__ float red[8];
    int c  = blockIdx.x / 24;
    int bd = blockIdx.x % 24;
    size_t base = (size_t)c * PCOLS + (size_t)bd * 1024 + threadIdx.x * 4;
    float4 a = *(const float4*)(Xs + base);
    float4 d = *(const float4*)(Dx + base);
    float4 h = make_float4(a.x + d.x, a.y + d.y, a.z + d.z, a.w + d.w);
    if (!last) *(float4*)(Hh + base) = h;
    float s = h.x + h.y + h.z + h.w;
    #pragma unroll
    for (int o = 16; o; o >>= 1) s += __shfl_down_sync(0xffffffffu, s, o);
    if ((threadIdx.x & 31) == 0) red[threadIdx.x >> 5] = s;
    __syncthreads();
    if (threadIdx.x == 0) {
        float tot = 0.f;
        #pragma unroll
        for (int i = 0; i < 8; i++) tot += red[i];
        P[c * 24 + bd] = tot * (1.f / N_);
    }
}

// ---------------------------------------------------------------------------
// Kernel 5: bias[m][bd] = sum_c W[m][128+c] * P[c][bd]   (tiny)
// ---------------------------------------------------------------------------
__global__ void bias_k(const float* __restrict__ W, int lda,
                       const float* __restrict__ P, float* __restrict__ out)
{
    int m = blockIdx.x, bd = threadIdx.x;   // 24 threads
    float s = 0.f;
    #pragma unroll 8
    for (int c = 0; c < 128; c++)
        s += W[(size_t)m * lda + 128 + c] * P[c * 24 + bd];
    out[m * 24 + bd] = s;
}

// ---------------------------------------------------------------------------
// Kernel 6: head — act = vn_lrelu(hidden, Wd@hidden, 0.2); out = Wc @ act
// hidden read from P128 ([c][b*3+d])
// ---------------------------------------------------------------------------
__global__ __launch_bounds__(128)
void head_kernel(const float* __restrict__ P, const float* __restrict__ Wd,
                 const float* __restrict__ Wc, float* __restrict__ out)
{
    __shared__ float hid[H_][3];
    __shared__ float act[H_][3];
    const int b = blockIdx.x, h = threadIdx.x;

    hid[h][0] = P[h * 24 + b * 3 + 0];
    hid[h][1] = P[h * 24 + b * 3 + 1];
    hid[h][2] = P[h * 24 + b * 3 + 2];
    __syncthreads();

    float d0 = 0.f, d1 = 0.f, d2 = 0.f;
    #pragma unroll 8
    for (int c = 0; c < H_; c++) {
        float w = Wd[h * H_ + c];
        d0 = fmaf(w, hid[c][0], d0);
        d1 = fmaf(w, hid[c][1], d1);
        d2 = fmaf(w, hid[c][2], d2);
    }
    float p0 = hid[h][0], p1 = hid[h][1], p2 = hid[h][2];
    float dot = p0 * d0 + p1 * d1 + p2 * d2;
    float dsq = d0 * d0 + d1 * d1 + d2 * d2;
    float f   = dot / (dsq + EPS_);
    bool  pos = (dot >= 0.f);
    act[h][0] = 0.2f * p0 + 0.8f * (pos ? p0 : p0 - f * d0);
    act[h][1] = 0.2f * p1 + 0.8f * (pos ? p1 : p1 - f * d1);
    act[h][2] = 0.2f * p2 + 0.8f * (pos ? p2 : p2 - f * d2);
    __syncthreads();

    float o0 = 0.f, o1 = 0.f, o2 = 0.f;
    #pragma unroll 8
    for (int c = 0; c < H_; c++) {
        float w = Wc[h * H_ + c];
        o0 = fmaf(w, act[c][0], o0);
        o1 = fmaf(w, act[c][1], o1);
        o2 = fmaf(w, act[c][2], o2);
    }
    out[b * (H_ * 3) + h * 3 + 0] = o0;
    out[b * (H_ * 3) + h * 3 + 1] = o1;
    out[b * (H_ * 3) + h * 3 + 2] = o2;
}

// ---------------------------------------------------------------------------
// launcher
// ---------------------------------------------------------------------------
extern "C" void kernel_launch(void* const* d_in, const int* in_sizes, int n_in,
                              void* d_out, int out_size)
{
    const float* x       = (const float*)d_in[0];
    const float* cpWf    = (const float*)d_in[1];
    const float* cpWd    = (const float*)d_in[2];
    const float* fcposW  = (const float*)d_in[3];   // (256,128)
    const float* blkWd0  = (const float*)d_in[4];   // (4,256,256)
    const float* blkW0   = (const float*)d_in[5];   // (4,128,256)
    const float* blkWd1  = (const float*)d_in[6];   // (4,128,128)
    const float* blkW1   = (const float*)d_in[7];   // (4,128,128)
    const float* blkWs   = (const float*)d_in[8];   // (4,128,256)
    const float* actWd   = (const float*)d_in[9];
    const float* fccW    = (const float*)d_in[10];
    float* out = (float*)d_out;

    float *H0, *T0, *T1, *T2, *T3, *T4, *P128, *bWd0, *bWs;
    cudaGetSymbolAddress((void**)&H0,   g_H0);
    cudaGetSymbolAddress((void**)&T0,   g_T0);
    cudaGetSymbolAddress((void**)&T1,   g_T1);
    cudaGetSymbolAddress((void**)&T2,   g_T2);
    cudaGetSymbolAddress((void**)&T3,   g_T3);
    cudaGetSymbolAddress((void**)&T4,   g_T4);
    cudaGetSymbolAddress((void**)&P128, g_P128);
    cudaGetSymbolAddress((void**)&bWd0, g_bWd0);
    cudaGetSymbolAddress((void**)&bWs,  g_bWs);

    const int NT = PCOLS / 64;   // 384 column tiles

    // stage A: knn + feature + conv_pos + mean_k -> T1 (128 x P)
    knn_conv_kernel<<<B_ * N_, 128>>>(x, cpWf, cpWd, T1);

    // fc_pos: H0(full 256 x P) = fc_pos_W @ T1
    gemm_tf32x3<<<dim3(NT, 2), 256>>>(fcposW, 128, T1, H0, 128, nullptr);

    for (int i = 0; i < 4; i++) {
        const float* Wd0 = blkWd0 + (size_t)i * 256 * 256;
        const float* W0  = blkW0  + (size_t)i * 128 * 256;
        const float* Wd1 = blkWd1 + (size_t)i * 128 * 128;
        const float* W1  = blkW1  + (size_t)i * 128 * 128;
        const float* Ws_ = blkWs  + (size_t)i * 128 * 256;
        const int Kin    = (i == 0) ? 256 : 128;
        const float* bd0 = (i == 0) ? nullptr : bWd0;
        const float* bs  = (i == 0) ? nullptr : bWs;
        const float* Pp  = (i == 0) ? nullptr : P128;

        // d0 = Wd0 @ hidden ; a0 = lrelu(hidden, d0, 0) in T0 (256 x P)
        gemm_tf32x3<<<dim3(NT, 2), 256>>>(Wd0, 256, H0, T0, Kin, bd0);
        vn_lrelu4<<<2048, 256>>>(H0, Pp, T0, 0.0f);

        // net = W0 @ a0 (128 x P)
        gemm_tf32x3<<<dim3(NT, 1), 256>>>(W0, 256, T0, T1, 256, nullptr);

        // d1 = Wd1 @ net ; a1 = lrelu(net, d1, 0) in T2
        gemm_tf32x3<<<dim3(NT, 1), 256>>>(Wd1, 128, T1, T2, 128, nullptr);
        vn_lrelu4<<<1024, 256>>>(T1, nullptr, T2, 0.0f);

        // dx = W1 @ a1 ; xs = Ws @ hidden
        gemm_tf32x3<<<dim3(NT, 1), 256>>>(W1, 128, T2, T3, 128, nullptr);
        gemm_tf32x3<<<dim3(NT, 1), 256>>>(Ws_, 256, H0, T4, Kin, bs);

        // h = xs + dx -> H0 (first 128 rows) ; pooled -> P128
        addpool4<<<H_ * 24, 256>>>(T4, T3, H0, P128, (i == 3) ? 1 : 0);

        // fold pooled half of next layer's Wd0/Ws into bias vectors
        if (i < 3) {
            bias_k<<<256, 24>>>(blkWd0 + (size_t)(i + 1) * 256 * 256, 256, P128, bWd0);
            bias_k<<<128, 24>>>(blkWs  + (size_t)(i + 1) * 128 * 256, 256, P128, bWs);
        }
    }

    head_kernel<<<B_, 128>>>(P128, actWd, fccW, out);

    (void)in_sizes; (void)n_in; (void)out_size;
}

// round 6
// speedup vs baseline: 2.3782x; 1.2421x over previous
#include <cuda_runtime.h>
#include <cuda_fp16.h>
#include <math_constants.h>
#include <cstdint>

// ---------------------------------------------------------------------------
// VN_Resnet_Encoder — B=8, N=1024, k=20, H=128, LAYER_NUM=4
// Column layout: col = (b*3 + d)*1024 + n,  P = 24576
// All activations/weights stored as split fp16 planes (hi + lo ~= fp32).
// GEMMs: mma.m16n8k16.f16 with 3-term split (fp32-grade accuracy).
// ---------------------------------------------------------------------------

#define B_      8
#define N_      1024
#define KNN_    20
#define H_      128
#define PCOLS   24576
#define EPS_    1e-6f

// ---------------- scratch (static device globals; no allocation) -----------
__device__ __half g_H0h[256 * PCOLS], g_H0l[256 * PCOLS];
__device__ __half g_T0h[256 * PCOLS], g_T0l[256 * PCOLS];
__device__ __half g_T1h[128 * PCOLS], g_T1l[128 * PCOLS];
__device__ __half g_T2h[128 * PCOLS], g_T2l[128 * PCOLS];
__device__ __half g_T3h[128 * PCOLS], g_T3l[128 * PCOLS];
__device__ __half g_T4h[128 * PCOLS], g_T4l[128 * PCOLS];
__device__ float  g_P128[H_ * 24];
__device__ float  g_bWd0[256 * 24];
__device__ float  g_bWs [128 * 24];

// pre-split weight pool (fp16 hi/lo planes)
#define OFF_FCPOS 0
#define OFF_WD0   32768
#define OFF_W0    294912
#define OFF_WD1   425984
#define OFF_W1    491520
#define OFF_WS    557056
#define WPOOL     688128
__device__ __half g_Wh[WPOOL], g_Wl[WPOOL];

// ---------------- helpers ---------------------------------------------------
__device__ __forceinline__ void split1(float v, __half& hi, __half& lo) {
    hi = __float2half_rn(v);
    lo = __float2half_rn(v - __half2float(hi));
}

// load 8 fp16 hi + 8 fp16 lo, reconstruct 8 fp32
__device__ __forceinline__ void ld8(const __half* ph, const __half* pl, float* out) {
    uint4 uh = *(const uint4*)ph;
    uint4 ul = *(const uint4*)pl;
    const __half2* hh = (const __half2*)&uh;
    const __half2* ll = (const __half2*)&ul;
    #pragma unroll
    for (int j = 0; j < 4; j++) {
        float2 fh = __half22float2(hh[j]);
        float2 fl = __half22float2(ll[j]);
        out[2 * j]     = fh.x + fl.x;
        out[2 * j + 1] = fh.y + fl.y;
    }
}

// split 8 fp32 into hi/lo planes and store as uint4 each
__device__ __forceinline__ void st8(const float* v, __half* ph, __half* pl) {
    uint4 uh, ul;
    __half2* hh = (__half2*)&uh;
    __half2* ll = (__half2*)&ul;
    #pragma unroll
    for (int j = 0; j < 4; j++) {
        __half a, b, c, d;
        split1(v[2 * j],     a, c);
        split1(v[2 * j + 1], b, d);
        hh[j] = __halves2half2(a, b);
        ll[j] = __halves2half2(c, d);
    }
    *(uint4*)ph = uh;
    *(uint4*)pl = ul;
}

// ---------------------------------------------------------------------------
// Kernel 0: split fp32 weights -> fp16 hi/lo pool
// ---------------------------------------------------------------------------
__global__ void convw_kernel(const float* __restrict__ src,
                             __half* __restrict__ dh, __half* __restrict__ dl, int n)
{
    int i = blockIdx.x * 256 + threadIdx.x;
    if (i >= n) return;
    __half hi, lo;
    split1(src[i], hi, lo);
    dh[i] = hi; dl[i] = lo;
}

// ---------------------------------------------------------------------------
// Kernel 1: KNN + graph feature cross + conv_pos + mean_k  (writes T1 planes)
// ---------------------------------------------------------------------------
__global__ __launch_bounds__(128)
void knn_conv_kernel(const float* __restrict__ x,
                     const float* __restrict__ Wf,
                     const float* __restrict__ Wd,
                     __half* __restrict__ Oh, __half* __restrict__ Ol)
{
    __shared__ float px[N_], py[N_], pz[N_];
    __shared__ float sc[N_];
    __shared__ int   nb[KNN_];
    __shared__ float wmax[4];
    __shared__ int   warg[4];

    const int b = blockIdx.x >> 10;
    const int n = blockIdx.x & 1023;
    const float* xb = x + (size_t)b * N_ * 3;

    for (int i = threadIdx.x; i < N_; i += 128) {
        px[i] = xb[i * 3 + 0];
        py[i] = xb[i * 3 + 1];
        pz[i] = xb[i * 3 + 2];
    }
    __syncthreads();

    const float cx = px[n], cy = py[n], cz = pz[n];

    for (int i = threadIdx.x; i < N_; i += 128) {
        float dx = px[i] - cx, dy = py[i] - cy, dz = pz[i] - cz;
        sc[i] = -(dx * dx + dy * dy + dz * dz);
    }
    __syncthreads();

    const int lane = threadIdx.x & 31, wrp = threadIdx.x >> 5;

    for (int kk = 0; kk < KNN_; kk++) {
        float best = -CUDART_INF_F;
        int   bi   = 1 << 30;
        for (int i = threadIdx.x; i < N_; i += 128) {
            float s = sc[i];
            if (s > best || (s == best && i < bi)) { best = s; bi = i; }
        }
        #pragma unroll
        for (int o = 16; o; o >>= 1) {
            float ob = __shfl_down_sync(0xffffffffu, best, o);
            int   oi = __shfl_down_sync(0xffffffffu, bi,   o);
            if (ob > best || (ob == best && oi < bi)) { best = ob; bi = oi; }
        }
        if (lane == 0) { wmax[wrp] = best; warg[wrp] = bi; }
        __syncthreads();
        if (threadIdx.x == 0) {
            float bb = wmax[0]; int ii = warg[0];
            #pragma unroll
            for (int w = 1; w < 4; w++)
                if (wmax[w] > bb || (wmax[w] == bb && warg[w] < ii)) { bb = wmax[w]; ii = warg[w]; }
            nb[kk] = ii;
            sc[ii] = -CUDART_INF_F;
        }
        __syncthreads();
    }

    const int h = threadIdx.x;
    const float wf0 = Wf[h * 3 + 0], wf1 = Wf[h * 3 + 1], wf2 = Wf[h * 3 + 2];
    const float wd0 = Wd[h * 3 + 0], wd1 = Wd[h * 3 + 1], wd2 = Wd[h * 3 + 2];

    float a0 = 0.f, a1 = 0.f, a2 = 0.f;
    #pragma unroll 4
    for (int kk = 0; kk < KNN_; kk++) {
        int j = nb[kk];
        float nx = px[j], ny = py[j], nz = pz[j];
        float e0 = nx - cx, e1 = ny - cy, e2 = nz - cz;
        float r0 = ny * cz - nz * cy;
        float r1 = nz * cx - nx * cz;
        float r2 = nx * cy - ny * cx;

        float pd0 = wf0 * e0 + wf1 * cx + wf2 * r0;
        float pd1 = wf0 * e1 + wf1 * cy + wf2 * r1;
        float pd2 = wf0 * e2 + wf1 * cz + wf2 * r2;
        float dd0 = wd0 * e0 + wd1 * cx + wd2 * r0;
        float dd1 = wd0 * e1 + wd1 * cy + wd2 * r1;
        float dd2 = wd0 * e2 + wd1 * cz + wd2 * r2;

        float dot = pd0 * dd0 + pd1 * dd1 + pd2 * dd2;
        float dsq = dd0 * dd0 + dd1 * dd1 + dd2 * dd2;
        float f   = dot / (dsq + EPS_);
        bool  pos = (dot >= 0.f);
        a0 += 0.2f * pd0 + 0.8f * (pos ? pd0 : pd0 - f * dd0);
        a1 += 0.2f * pd1 + 0.8f * (pos ? pd1 : pd1 - f * dd1);
        a2 += 0.2f * pd2 + 0.8f * (pos ? pd2 : pd2 - f * dd2);
    }

    size_t base = (size_t)h * PCOLS + (size_t)b * 3 * N_ + n;
    __half hi, lo;
    split1(a0 * (1.0f / KNN_), hi, lo); Oh[base         ] = hi; Ol[base         ] = lo;
    split1(a1 * (1.0f / KNN_), hi, lo); Oh[base + N_    ] = hi; Ol[base + N_    ] = lo;
    split1(a2 * (1.0f / KNN_), hi, lo); Oh[base + 2 * N_] = hi; Ol[base + 2 * N_] = lo;
}

// ---------------------------------------------------------------------------
// Kernel 2: split-fp16 x3 tensor-core GEMM.
// C = W(MxK, lda) @ X(KxP).  BM=128, BN=64, BK=32. 8 warps (4m x 2n).
// Inputs/outputs are hi/lo fp16 planes. bias[m][bd] optional.
// ---------------------------------------------------------------------------
#define MMA_F16(c0,c1,c2,c3,a0,a1,a2,a3,b0,b1)                               \
    asm volatile("mma.sync.aligned.m16n8k16.row.col.f32.f16.f16.f32 "        \
        "{%0,%1,%2,%3},{%4,%5,%6,%7},{%8,%9},{%0,%1,%2,%3};"                 \
        : "+f"(c0),"+f"(c1),"+f"(c2),"+f"(c3)                                \
        : "r"(a0),"r"(a1),"r"(a2),"r"(a3),"r"(b0),"r"(b1))

__global__ __launch_bounds__(256)
void gemm_f16x3(const __half* __restrict__ Wh, const __half* __restrict__ Wl, int lda,
                const __half* __restrict__ Xh, const __half* __restrict__ Xl,
                __half* __restrict__ Ch, __half* __restrict__ Cl,
                int K, const float* __restrict__ bias)
{
    // half2 {k,k+1} stored at [k2][m] / [k2][n]; pads -> conflict-free LDS
    __shared__ uint32_t Ahs[16][136];
    __shared__ uint32_t Als[16][136];
    __shared__ uint32_t Bhs[16][72];
    __shared__ uint32_t Bls[16][72];
    __shared__ float    bsh[128];

    const int t    = threadIdx.x;
    const int p0   = blockIdx.x * 64;
    const int m0   = blockIdx.y * 128;
    const int warp = t >> 5, lane = t & 31;
    const int wm   = (warp & 3) * 32;
    const int wn   = (warp >> 2) * 32;
    const int g    = lane >> 2, tg = lane & 3;

    if (t < 128) bsh[t] = bias ? bias[(m0 + t) * 24 + (p0 >> 10)] : 0.0f;

    float acc[2][4][4];
    #pragma unroll
    for (int i = 0; i < 2; i++)
        #pragma unroll
        for (int j = 0; j < 4; j++)
            #pragma unroll
            for (int l = 0; l < 4; l++) acc[i][j][l] = 0.f;

    for (int k0 = 0; k0 < K; k0 += 32) {
        // --- stage A (W tile 128 x 32): pure copy of pre-split fp16 ---
        #pragma unroll
        for (int i = 0; i < 2; i++) {
            int idx = t + i * 256;           // 0..511
            int m   = idx >> 2;              // 0..127
            int oct = idx & 3;               // k-octet (8 fp16)
            const size_t go = (size_t)(m0 + m) * lda + k0 + oct * 8;
            uint4 vh = *(const uint4*)(Wh + go);
            uint4 vl = *(const uint4*)(Wl + go);
            int k2 = oct * 4;
            Ahs[k2 + 0][m] = vh.x; Ahs[k2 + 1][m] = vh.y;
            Ahs[k2 + 2][m] = vh.z; Ahs[k2 + 3][m] = vh.w;
            Als[k2 + 0][m] = vl.x; Als[k2 + 1][m] = vl.y;
            Als[k2 + 2][m] = vl.z; Als[k2 + 3][m] = vl.w;
        }
        // --- stage B (X tile 32 x 64): interleave rows k,k+1 into half2 ---
        {
            int kp = t >> 4;                 // 0..15 (k-pair)
            int cg = t & 15;                 // 0..15 (4-col group)
            const size_t go = (size_t)(k0 + 2 * kp) * PCOLS + p0 + cg * 4;
            uint2 uh0 = *(const uint2*)(Xh + go);
            uint2 uh1 = *(const uint2*)(Xh + go + PCOLS);
            uint2 ul0 = *(const uint2*)(Xl + go);
            uint2 ul1 = *(const uint2*)(Xl + go + PCOLS);
            int c4 = cg * 4;
            Bhs[kp][c4 + 0] = __byte_perm(uh0.x, uh1.x, 0x5410);
            Bhs[kp][c4 + 1] = __byte_perm(uh0.x, uh1.x, 0x7632);
            Bhs[kp][c4 + 2] = __byte_perm(uh0.y, uh1.y, 0x5410);
            Bhs[kp][c4 + 3] = __byte_perm(uh0.y, uh1.y, 0x7632);
            Bls[kp][c4 + 0] = __byte_perm(ul0.x, ul1.x, 0x5410);
            Bls[kp][c4 + 1] = __byte_perm(ul0.x, ul1.x, 0x7632);
            Bls[kp][c4 + 2] = __byte_perm(ul0.y, ul1.y, 0x5410);
            Bls[kp][c4 + 3] = __byte_perm(ul0.y, ul1.y, 0x7632);
        }
        __syncthreads();

        #pragma unroll
        for (int s = 0; s < 2; s++) {
            const int kb = s * 8;
            uint32_t ah[2][4], al[2][4];
            #pragma unroll
            for (int mt = 0; mt < 2; mt++) {
                int rr = wm + mt * 16 + g;
                ah[mt][0] = Ahs[kb + tg    ][rr    ];  al[mt][0] = Als[kb + tg    ][rr    ];
                ah[mt][1] = Ahs[kb + tg    ][rr + 8];  al[mt][1] = Als[kb + tg    ][rr + 8];
                ah[mt][2] = Ahs[kb + tg + 4][rr    ];  al[mt][2] = Als[kb + tg + 4][rr    ];
                ah[mt][3] = Ahs[kb + tg + 4][rr + 8];  al[mt][3] = Als[kb + tg + 4][rr + 8];
            }
            #pragma unroll
            for (int nt = 0; nt < 4; nt++) {
                int cc = wn + nt * 8 + g;
                uint32_t bh0 = Bhs[kb + tg    ][cc];
                uint32_t bh1 = Bhs[kb + tg + 4][cc];
                uint32_t bl0 = Bls[kb + tg    ][cc];
                uint32_t bl1 = Bls[kb + tg + 4][cc];
                #pragma unroll
                for (int mt = 0; mt < 2; mt++) {
                    MMA_F16(acc[mt][nt][0], acc[mt][nt][1], acc[mt][nt][2], acc[mt][nt][3],
                            al[mt][0], al[mt][1], al[mt][2], al[mt][3], bh0, bh1);
                    MMA_F16(acc[mt][nt][0], acc[mt][nt][1], acc[mt][nt][2], acc[mt][nt][3],
                            ah[mt][0], ah[mt][1], ah[mt][2], ah[mt][3], bl0, bl1);
                    MMA_F16(acc[mt][nt][0], acc[mt][nt][1], acc[mt][nt][2], acc[mt][nt][3],
                            ah[mt][0], ah[mt][1], ah[mt][2], ah[mt][3], bh0, bh1);
                }
            }
        }
        __syncthreads();
    }

    // epilogue: add bias, split to hi/lo fp16 planes
    #pragma unroll
    for (int mt = 0; mt < 2; mt++) {
        int r0 = wm + mt * 16 + g;
        float b0v = bsh[r0], b1v = bsh[r0 + 8];
        #pragma unroll
        for (int nt = 0; nt < 4; nt++) {
            int col = p0 + wn + nt * 8 + 2 * tg;
            float v00 = acc[mt][nt][0] + b0v, v01 = acc[mt][nt][1] + b0v;
            float v10 = acc[mt][nt][2] + b1v, v11 = acc[mt][nt][3] + b1v;
            __half h00, l00, h01, l01, h10, l10, h11, l11;
            split1(v00, h00, l00); split1(v01, h01, l01);
            split1(v10, h10, l10); split1(v11, h11, l11);
            size_t o0 = (size_t)(m0 + r0    ) * PCOLS + col;
            size_t o1 = (size_t)(m0 + r0 + 8) * PCOLS + col;
            *(__half2*)(Ch + o0) = __halves2half2(h00, h01);
            *(__half2*)(Cl + o0) = __halves2half2(l00, l01);
            *(__half2*)(Ch + o1) = __halves2half2(h10, h11);
            *(__half2*)(Cl + o1) = __halves2half2(l10, l11);
        }
    }
}

// ---------------------------------------------------------------------------
// Kernel 3: VN leaky-relu on planes. p from (Ph,Pl) for c<128 (or Pp==null),
// pooled vector Pp for c>=128. Output overwrites (Dh,Dl). 8 cols per thread.
// ---------------------------------------------------------------------------
__global__ __launch_bounds__(256)
void vn_lrelu_h(const __half* __restrict__ Ph, const __half* __restrict__ Pl,
                const float* __restrict__ Pp,
                __half* __restrict__ Dh, __half* __restrict__ Dl, float slope)
{
    int idx = blockIdx.x * 256 + threadIdx.x;   // c * 1024 + r
    int c  = idx >> 10;
    int r  = idx & 1023;
    int b  = r >> 7;
    int n8 = (r & 127) << 3;
    size_t base = (size_t)c * PCOLS + (size_t)b * 3072 + n8;

    float D0[8], D1[8], D2[8];
    ld8(Dh + base,        Dl + base,        D0);
    ld8(Dh + base + 1024, Dl + base + 1024, D1);
    ld8(Dh + base + 2048, Dl + base + 2048, D2);

    float P0[8], P1[8], P2[8];
    if (Pp != nullptr && c >= 128) {
        float v0 = Pp[(c - 128) * 24 + b * 3 + 0];
        float v1 = Pp[(c - 128) * 24 + b * 3 + 1];
        float v2 = Pp[(c - 128) * 24 + b * 3 + 2];
        #pragma unroll
        for (int j = 0; j < 8; j++) { P0[j] = v0; P1[j] = v1; P2[j] = v2; }
    } else {
        ld8(Ph + base,        Pl + base,        P0);
        ld8(Ph + base + 1024, Pl + base + 1024, P1);
        ld8(Ph + base + 2048, Pl + base + 2048, P2);
    }

    float O0[8], O1[8], O2[8];
    const float om = 1.f - slope;
    #pragma unroll
    for (int j = 0; j < 8; j++) {
        float dot = P0[j] * D0[j] + P1[j] * D1[j] + P2[j] * D2[j];
        float dsq = D0[j] * D0[j] + D1[j] * D1[j] + D2[j] * D2[j];
        float f   = dot / (dsq + EPS_);
        bool  pos = (dot >= 0.f);
        O0[j] = slope * P0[j] + om * (pos ? P0[j] : P0[j] - f * D0[j]);
        O1[j] = slope * P1[j] + om * (pos ? P1[j] : P1[j] - f * D1[j]);
        O2[j] = slope * P2[j] + om * (pos ? P2[j] : P2[j] - f * D2[j]);
    }
    st8(O0, Dh + base,        Dl + base);
    st8(O1, Dh + base + 1024, Dl + base + 1024);
    st8(O2, Dh + base + 2048, Dl + base + 2048);
}

// ---------------------------------------------------------------------------
// Kernel 4: h = xs + dx -> H0 planes (unless last) ; pooled -> P128[c][bd]
// one block per (c, bd); 128 threads x 8 cols
// ---------------------------------------------------------------------------
__global__ __launch_bounds__(128)
void addpool_h(const __half* __restrict__ Xh, const __half* __restrict__ Xl,
               const __half* __restrict__ Dxh, const __half* __restrict__ Dxl,
               __half* __restrict__ Hh, __half* __restrict__ Hl,
               float* __restrict__ P, int last)
{
    __shared__ float red[4];
    int c  = blockIdx.x / 24;
    int bd = blockIdx.x % 24;
    size_t base = (size_t)c * PCOLS + (size_t)bd * 1024 + threadIdx.x * 8;

    float a[8], d[8], h[8];
    ld8(Xh + base,  Xl + base,  a);
    ld8(Dxh + base, Dxl + base, d);
    float s = 0.f;
    #pragma unroll
    for (int j = 0; j < 8; j++) { h[j] = a[j] + d[j]; s += h[j]; }
    if (!last) st8(h, Hh + base, Hl + base);

    #pragma unroll
    for (int o = 16; o; o >>= 1) s += __shfl_down_sync(0xffffffffu, s, o);
    if ((threadIdx.x & 31) == 0) red[threadIdx.x >> 5] = s;
    __syncthreads();
    if (threadIdx.x == 0)
        P[c * 24 + bd] = (red[0] + red[1] + red[2] + red[3]) * (1.f / N_);
}

// ---------------------------------------------------------------------------
// Kernel 5: bias[m][bd] = sum_c W[m][128+c] * P[c][bd]   (fp32 weights)
// ---------------------------------------------------------------------------
__global__ void bias_k(const float* __restrict__ W, int lda,
                       const float* __restrict__ P, float* __restrict__ out)
{
    int m = blockIdx.x, bd = threadIdx.x;   // 24 threads
    float s = 0.f;
    #pragma unroll 8
    for (int c = 0; c < 128; c++)
        s += W[(size_t)m * lda + 128 + c] * P[c * 24 + bd];
    out[m * 24 + bd] = s;
}

// ---------------------------------------------------------------------------
// Kernel 6: head (fp32, tiny)
// ---------------------------------------------------------------------------
__global__ __launch_bounds__(128)
void head_kernel(const float* __restrict__ P, const float* __restrict__ Wd,
                 const float* __restrict__ Wc, float* __restrict__ out)
{
    __shared__ float hid[H_][3];
    __shared__ float act[H_][3];
    const int b = blockIdx.x, h = threadIdx.x;

    hid[h][0] = P[h * 24 + b * 3 + 0];
    hid[h][1] = P[h * 24 + b * 3 + 1];
    hid[h][2] = P[h * 24 + b * 3 + 2];
    __syncthreads();

    float d0 = 0.f, d1 = 0.f, d2 = 0.f;
    #pragma unroll 8
    for (int c = 0; c < H_; c++) {
        float w = Wd[h * H_ + c];
        d0 = fmaf(w, hid[c][0], d0);
        d1 = fmaf(w, hid[c][1], d1);
        d2 = fmaf(w, hid[c][2], d2);
    }
    float p0 = hid[h][0], p1 = hid[h][1], p2 = hid[h][2];
    float dot = p0 * d0 + p1 * d1 + p2 * d2;
    float dsq = d0 * d0 + d1 * d1 + d2 * d2;
    float f   = dot / (dsq + EPS_);
    bool  pos = (dot >= 0.f);
    act[h][0] = 0.2f * p0 + 0.8f * (pos ? p0 : p0 - f * d0);
    act[h][1] = 0.2f * p1 + 0.8f * (pos ? p1 : p1 - f * d1);
    act[h][2] = 0.2f * p2 + 0.8f * (pos ? p2 : p2 - f * d2);
    __syncthreads();

    float o0 = 0.f, o1 = 0.f, o2 = 0.f;
    #pragma unroll 8
    for (int c = 0; c < H_; c++) {
        float w = Wc[h * H_ + c];
        o0 = fmaf(w, act[c][0], o0);
        o1 = fmaf(w, act[c][1], o1);
        o2 = fmaf(w, act[c][2], o2);
    }
    out[b * (H_ * 3) + h * 3 + 0] = o0;
    out[b * (H_ * 3) + h * 3 + 1] = o1;
    out[b * (H_ * 3) + h * 3 + 2] = o2;
}

// ---------------------------------------------------------------------------
// launcher
// ---------------------------------------------------------------------------
extern "C" void kernel_launch(void* const* d_in, const int* in_sizes, int n_in,
                              void* d_out, int out_size)
{
    const float* x       = (const float*)d_in[0];
    const float* cpWf    = (const float*)d_in[1];
    const float* cpWd    = (const float*)d_in[2];
    const float* fcposW  = (const float*)d_in[3];   // (256,128)
    const float* blkWd0  = (const float*)d_in[4];   // (4,256,256)
    const float* blkW0   = (const float*)d_in[5];   // (4,128,256)
    const float* blkWd1  = (const float*)d_in[6];   // (4,128,128)
    const float* blkW1   = (const float*)d_in[7];   // (4,128,128)
    const float* blkWs   = (const float*)d_in[8];   // (4,128,256)
    const float* actWd   = (const float*)d_in[9];
    const float* fccW    = (const float*)d_in[10];
    float* out = (float*)d_out;

    __half *H0h, *H0l, *T0h, *T0l, *T1h, *T1l, *T2h, *T2l, *T3h, *T3l, *T4h, *T4l;
    __half *Wh, *Wl;
    float *P128, *bWd0, *bWs;
    cudaGetSymbolAddress((void**)&H0h, g_H0h); cudaGetSymbolAddress((void**)&H0l, g_H0l);
    cudaGetSymbolAddress((void**)&T0h, g_T0h); cudaGetSymbolAddress((void**)&T0l, g_T0l);
    cudaGetSymbolAddress((void**)&T1h, g_T1h); cudaGetSymbolAddress((void**)&T1l, g_T1l);
    cudaGetSymbolAddress((void**)&T2h, g_T2h); cudaGetSymbolAddress((void**)&T2l, g_T2l);
    cudaGetSymbolAddress((void**)&T3h, g_T3h); cudaGetSymbolAddress((void**)&T3l, g_T3l);
    cudaGetSymbolAddress((void**)&T4h, g_T4h); cudaGetSymbolAddress((void**)&T4l, g_T4l);
    cudaGetSymbolAddress((void**)&Wh,  g_Wh);  cudaGetSymbolAddress((void**)&Wl,  g_Wl);
    cudaGetSymbolAddress((void**)&P128, g_P128);
    cudaGetSymbolAddress((void**)&bWd0, g_bWd0);
    cudaGetSymbolAddress((void**)&bWs,  g_bWs);

    // pre-split all GEMM weights (runs concurrently with knn)
    convw_kernel<<<(32768  + 255) / 256, 256>>>(fcposW, Wh + OFF_FCPOS, Wl + OFF_FCPOS, 32768);
    convw_kernel<<<(262144 + 255) / 256, 256>>>(blkWd0, Wh + OFF_WD0,   Wl + OFF_WD0,   262144);
    convw_kernel<<<(131072 + 255) / 256, 256>>>(blkW0,  Wh + OFF_W0,    Wl + OFF_W0,    131072);
    convw_kernel<<<(65536  + 255) / 256, 256>>>(blkWd1, Wh + OFF_WD1,   Wl + OFF_WD1,   65536);
    convw_kernel<<<(65536  + 255) / 256, 256>>>(blkW1,  Wh + OFF_W1,    Wl + OFF_W1,    65536);
    convw_kernel<<<(131072 + 255) / 256, 256>>>(blkWs,  Wh + OFF_WS,    Wl + OFF_WS,    131072);

    const int NT = PCOLS / 64;   // 384 column tiles

    // stage A: knn + feature + conv_pos + mean_k -> T1 planes (128 x P)
    knn_conv_kernel<<<B_ * N_, 128>>>(x, cpWf, cpWd, T1h, T1l);

    // fc_pos: H0 (256 x P) = fc_pos_W @ T1
    gemm_f16x3<<<dim3(NT, 2), 256>>>(Wh + OFF_FCPOS, Wl + OFF_FCPOS, 128,
                                     T1h, T1l, H0h, H0l, 128, nullptr);

    for (int i = 0; i < 4; i++) {
        const __half* Wd0h = Wh + OFF_WD0 + (size_t)i * 65536;
        const __half* Wd0l = Wl + OFF_WD0 + (size_t)i * 65536;
        const __half* W0h  = Wh + OFF_W0  + (size_t)i * 32768;
        const __half* W0l  = Wl + OFF_W0  + (size_t)i * 32768;
        const __half* Wd1h = Wh + OFF_WD1 + (size_t)i * 16384;
        const __half* Wd1l = Wl + OFF_WD1 + (size_t)i * 16384;
        const __half* W1h  = Wh + OFF_W1  + (size_t)i * 16384;
        const __half* W1l  = Wl + OFF_W1  + (size_t)i * 16384;
        const __half* Wsh  = Wh + OFF_WS  + (size_t)i * 32768;
        const __half* Wsl  = Wl + OFF_WS  + (size_t)i * 32768;
        const int Kin    = (i == 0) ? 256 : 128;
        const float* bd0 = (i == 0) ? nullptr : bWd0;
        const float* bs  = (i == 0) ? nullptr : bWs;
        const float* Pp  = (i == 0) ? nullptr : P128;

        // d0 = Wd0 @ hidden ; a0 = lrelu(hidden, d0, 0) in T0 (256 x P)
        gemm_f16x3<<<dim3(NT, 2), 256>>>(Wd0h, Wd0l, 256, H0h, H0l, T0h, T0l, Kin, bd0);
        vn_lrelu_h<<<1024, 256>>>(H0h, H0l, Pp, T0h, T0l, 0.0f);

        // net = W0 @ a0 (128 x P)
        gemm_f16x3<<<dim3(NT, 1), 256>>>(W0h, W0l, 256, T0h, T0l, T1h, T1l, 256, nullptr);

        // d1 = Wd1 @ net ; a1 = lrelu(net, d1, 0) in T2
        gemm_f16x3<<<dim3(NT, 1), 256>>>(Wd1h, Wd1l, 128, T1h, T1l, T2h, T2l, 128, nullptr);
        vn_lrelu_h<<<512, 256>>>(T1h, T1l, nullptr, T2h, T2l, 0.0f);

        // dx = W1 @ a1 ; xs = Ws @ hidden
        gemm_f16x3<<<dim3(NT, 1), 256>>>(W1h, W1l, 128, T2h, T2l, T3h, T3l, 128, nullptr);
        gemm_f16x3<<<dim3(NT, 1), 256>>>(Wsh, Wsl, 256, H0h, H0l, T4h, T4l, Kin, bs);

        // h = xs + dx -> H0 planes ; pooled -> P128
        addpool_h<<<H_ * 24, 128>>>(T4h, T4l, T3h, T3l, H0h, H0l, P128, (i == 3) ? 1 : 0);

        // fold pooled half of next layer's Wd0/Ws into bias vectors
        if (i < 3) {
            bias_k<<<256, 24>>>(blkWd0 + (size_t)(i + 1) * 256 * 256, 256, P128, bWd0);
            bias_k<<<128, 24>>>(blkWs  + (size_t)(i + 1) * 128 * 256, 256, P128, bWs);
        }
    }

    head_kernel<<<B_, 128>>>(P128, actWd, fccW, out);

    (void)in_sizes; (void)n_in; (void)out_size;
}

// round 7
// speedup vs baseline: 2.3894x; 1.0047x over previous
#include <cuda_runtime.h>
#include <cuda_fp16.h>
#include <math_constants.h>
#include <cstdint>

// ---------------------------------------------------------------------------
// VN_Resnet_Encoder — B=8, N=1024, k=20, H=128, LAYER_NUM=4
// Column layout: col = (b*3 + d)*1024 + n,  P = 24576
// All activations/weights stored as split fp16 planes (hi + lo ~= fp32).
// GEMMs: mma.m16n8k16.f16 with 3-term split (fp32-grade accuracy).
// ---------------------------------------------------------------------------

#define B_      8
#define N_      1024
#define KNN_    20
#define H_      128
#define PCOLS   24576
#define EPS_    1e-6f

// ---------------- scratch (static device globals; no allocation) -----------
__device__ __half g_H0h[256 * PCOLS], g_H0l[256 * PCOLS];
__device__ __half g_T0h[256 * PCOLS], g_T0l[256 * PCOLS];
__device__ __half g_T1h[128 * PCOLS], g_T1l[128 * PCOLS];
__device__ __half g_T2h[128 * PCOLS], g_T2l[128 * PCOLS];
__device__ __half g_T3h[128 * PCOLS], g_T3l[128 * PCOLS];
__device__ __half g_T4h[128 * PCOLS], g_T4l[128 * PCOLS];
__device__ float  g_P128[H_ * 24];
__device__ float  g_bWd0[256 * 24];
__device__ float  g_bWs [128 * 24];

// pre-split weight pool (fp16 hi/lo planes)
#define OFF_FCPOS 0
#define OFF_WD0   32768
#define OFF_W0    294912
#define OFF_WD1   425984
#define OFF_W1    491520
#define OFF_WS    557056
#define WPOOL     688128
__device__ __half g_Wh[WPOOL], g_Wl[WPOOL];

// ---------------- helpers ---------------------------------------------------
__device__ __forceinline__ void split1(float v, __half& hi, __half& lo) {
    hi = __float2half_rn(v);
    lo = __float2half_rn(v - __half2float(hi));
}

// load 8 fp16 hi + 8 fp16 lo, reconstruct 8 fp32
__device__ __forceinline__ void ld8(const __half* ph, const __half* pl, float* out) {
    uint4 uh = *(const uint4*)ph;
    uint4 ul = *(const uint4*)pl;
    const __half2* hh = (const __half2*)&uh;
    const __half2* ll = (const __half2*)&ul;
    #pragma unroll
    for (int j = 0; j < 4; j++) {
        float2 fh = __half22float2(hh[j]);
        float2 fl = __half22float2(ll[j]);
        out[2 * j]     = fh.x + fl.x;
        out[2 * j + 1] = fh.y + fl.y;
    }
}

// split 8 fp32 into hi/lo planes and store as uint4 each
__device__ __forceinline__ void st8(const float* v, __half* ph, __half* pl) {
    uint4 uh, ul;
    __half2* hh = (__half2*)&uh;
    __half2* ll = (__half2*)&ul;
    #pragma unroll
    for (int j = 0; j < 4; j++) {
        __half a, b, c, d;
        split1(v[2 * j],     a, c);
        split1(v[2 * j + 1], b, d);
        hh[j] = __halves2half2(a, b);
        ll[j] = __halves2half2(c, d);
    }
    *(uint4*)ph = uh;
    *(uint4*)pl = ul;
}

// ---------------------------------------------------------------------------
// Kernel 0: split fp32 weights -> fp16 hi/lo pool
// ---------------------------------------------------------------------------
__global__ void convw_kernel(const float* __restrict__ src,
                             __half* __restrict__ dh, __half* __restrict__ dl, int n)
{
    int i = blockIdx.x * 256 + threadIdx.x;
    if (i >= n) return;
    __half hi, lo;
    split1(src[i], hi, lo);
    dh[i] = hi; dl[i] = lo;
}

// ---------------------------------------------------------------------------
// Kernel 1: KNN + graph feature cross + conv_pos + mean_k  (writes T1 planes)
// ---------------------------------------------------------------------------
__global__ __launch_bounds__(128)
void knn_conv_kernel(const float* __restrict__ x,
                     const float* __restrict__ Wf,
                     const float* __restrict__ Wd,
                     __half* __restrict__ Oh, __half* __restrict__ Ol)
{
    __shared__ float px[N_], py[N_], pz[N_];
    __shared__ float sc[N_];
    __shared__ int   nb[KNN_];
    __shared__ float wmax[4];
    __shared__ int   warg[4];

    const int b = blockIdx.x >> 10;
    const int n = blockIdx.x & 1023;
    const float* xb = x + (size_t)b * N_ * 3;

    for (int i = threadIdx.x; i < N_; i += 128) {
        px[i] = xb[i * 3 + 0];
        py[i] = xb[i * 3 + 1];
        pz[i] = xb[i * 3 + 2];
    }
    __syncthreads();

    const float cx = px[n], cy = py[n], cz = pz[n];

    for (int i = threadIdx.x; i < N_; i += 128) {
        float dx = px[i] - cx, dy = py[i] - cy, dz = pz[i] - cz;
        sc[i] = -(dx * dx + dy * dy + dz * dz);
    }
    __syncthreads();

    const int lane = threadIdx.x & 31, wrp = threadIdx.x >> 5;

    for (int kk = 0; kk < KNN_; kk++) {
        float best = -CUDART_INF_F;
        int   bi   = 1 << 30;
        for (int i = threadIdx.x; i < N_; i += 128) {
            float s = sc[i];
            if (s > best || (s == best && i < bi)) { best = s; bi = i; }
        }
        #pragma unroll
        for (int o = 16; o; o >>= 1) {
            float ob = __shfl_down_sync(0xffffffffu, best, o);
            int   oi = __shfl_down_sync(0xffffffffu, bi,   o);
            if (ob > best || (ob == best && oi < bi)) { best = ob; bi = oi; }
        }
        if (lane == 0) { wmax[wrp] = best; warg[wrp] = bi; }
        __syncthreads();
        if (threadIdx.x == 0) {
            float bb = wmax[0]; int ii = warg[0];
            #pragma unroll
            for (int w = 1; w < 4; w++)
                if (wmax[w] > bb || (wmax[w] == bb && warg[w] < ii)) { bb = wmax[w]; ii = warg[w]; }
            nb[kk] = ii;
            sc[ii] = -CUDART_INF_F;
        }
        __syncthreads();
    }

    const int h = threadIdx.x;
    const float wf0 = Wf[h * 3 + 0], wf1 = Wf[h * 3 + 1], wf2 = Wf[h * 3 + 2];
    const float wd0 = Wd[h * 3 + 0], wd1 = Wd[h * 3 + 1], wd2 = Wd[h * 3 + 2];

    float a0 = 0.f, a1 = 0.f, a2 = 0.f;
    #pragma unroll 4
    for (int kk = 0; kk < KNN_; kk++) {
        int j = nb[kk];
        float nx = px[j], ny = py[j], nz = pz[j];
        float e0 = nx - cx, e1 = ny - cy, e2 = nz - cz;
        float r0 = ny * cz - nz * cy;
        float r1 = nz * cx - nx * cz;
        float r2 = nx * cy - ny * cx;

        float pd0 = wf0 * e0 + wf1 * cx + wf2 * r0;
        float pd1 = wf0 * e1 + wf1 * cy + wf2 * r1;
        float pd2 = wf0 * e2 + wf1 * cz + wf2 * r2;
        float dd0 = wd0 * e0 + wd1 * cx + wd2 * r0;
        float dd1 = wd0 * e1 + wd1 * cy + wd2 * r1;
        float dd2 = wd0 * e2 + wd1 * cz + wd2 * r2;

        float dot = pd0 * dd0 + pd1 * dd1 + pd2 * dd2;
        float dsq = dd0 * dd0 + dd1 * dd1 + dd2 * dd2;
        float f   = dot / (dsq + EPS_);
        bool  pos = (dot >= 0.f);
        a0 += 0.2f * pd0 + 0.8f * (pos ? pd0 : pd0 - f * dd0);
        a1 += 0.2f * pd1 + 0.8f * (pos ? pd1 : pd1 - f * dd1);
        a2 += 0.2f * pd2 + 0.8f * (pos ? pd2 : pd2 - f * dd2);
    }

    size_t base = (size_t)h * PCOLS + (size_t)b * 3 * N_ + n;
    __half hi, lo;
    split1(a0 * (1.0f / KNN_), hi, lo); Oh[base         ] = hi; Ol[base         ] = lo;
    split1(a1 * (1.0f / KNN_), hi, lo); Oh[base + N_    ] = hi; Ol[base + N_    ] = lo;
    split1(a2 * (1.0f / KNN_), hi, lo); Oh[base + 2 * N_] = hi; Ol[base + 2 * N_] = lo;
}

// ---------------------------------------------------------------------------
// Kernel 2: split-fp16 x3 tensor-core GEMM.
// C = W(MxK, lda) @ X(KxP).  BM=128, BN=64, BK=32. 8 warps (4m x 2n).
// Inputs/outputs are hi/lo fp16 planes. bias[m][bd] optional.
// ---------------------------------------------------------------------------
#define MMA_F16(c0,c1,c2,c3,a0,a1,a2,a3,b0,b1)                               \
    asm volatile("mma.sync.aligned.m16n8k16.row.col.f32.f16.f16.f32 "        \
        "{%0,%1,%2,%3},{%4,%5,%6,%7},{%8,%9},{%0,%1,%2,%3};"                 \
        : "+f"(c0),"+f"(c1),"+f"(c2),"+f"(c3)                                \
        : "r"(a0),"r"(a1),"r"(a2),"r"(a3),"r"(b0),"r"(b1))

__global__ __launch_bounds__(256)
void gemm_f16x3(const __half* __restrict__ Wh, const __half* __restrict__ Wl, int lda,
                const __half* __restrict__ Xh, const __half* __restrict__ Xl,
                __half* __restrict__ Ch, __half* __restrict__ Cl,
                int K, const float* __restrict__ bias)
{
    // half2 {k,k+1} stored at [k2][m] / [k2][n]; pads -> conflict-free LDS
    __shared__ uint32_t Ahs[16][136];
    __shared__ uint32_t Als[16][136];
    __shared__ uint32_t Bhs[16][72];
    __shared__ uint32_t Bls[16][72];
    __shared__ float    bsh[128];

    const int t    = threadIdx.x;
    const int p0   = blockIdx.x * 64;
    const int m0   = blockIdx.y * 128;
    const int warp = t >> 5, lane = t & 31;
    const int wm   = (warp & 3) * 32;
    const int wn   = (warp >> 2) * 32;
    const int g    = lane >> 2, tg = lane & 3;

    if (t < 128) bsh[t] = bias ? bias[(m0 + t) * 24 + (p0 >> 10)] : 0.0f;

    float acc[2][4][4];
    #pragma unroll
    for (int i = 0; i < 2; i++)
        #pragma unroll
        for (int j = 0; j < 4; j++)
            #pragma unroll
            for (int l = 0; l < 4; l++) acc[i][j][l] = 0.f;

    for (int k0 = 0; k0 < K; k0 += 32) {
        // --- stage A (W tile 128 x 32): pure copy of pre-split fp16 ---
        #pragma unroll
        for (int i = 0; i < 2; i++) {
            int idx = t + i * 256;           // 0..511
            int m   = idx >> 2;              // 0..127
            int oct = idx & 3;               // k-octet (8 fp16)
            const size_t go = (size_t)(m0 + m) * lda + k0 + oct * 8;
            uint4 vh = *(const uint4*)(Wh + go);
            uint4 vl = *(const uint4*)(Wl + go);
            int k2 = oct * 4;
            Ahs[k2 + 0][m] = vh.x; Ahs[k2 + 1][m] = vh.y;
            Ahs[k2 + 2][m] = vh.z; Ahs[k2 + 3][m] = vh.w;
            Als[k2 + 0][m] = vl.x; Als[k2 + 1][m] = vl.y;
            Als[k2 + 2][m] = vl.z; Als[k2 + 3][m] = vl.w;
        }
        // --- stage B (X tile 32 x 64): interleave rows k,k+1 into half2 ---
        {
            int kp = t >> 4;                 // 0..15 (k-pair)
            int cg = t & 15;                 // 0..15 (4-col group)
            const size_t go = (size_t)(k0 + 2 * kp) * PCOLS + p0 + cg * 4;
            uint2 uh0 = *(const uint2*)(Xh + go);
            uint2 uh1 = *(const uint2*)(Xh + go + PCOLS);
            uint2 ul0 = *(const uint2*)(Xl + go);
            uint2 ul1 = *(const uint2*)(Xl + go + PCOLS);
            int c4 = cg * 4;
            Bhs[kp][c4 + 0] = __byte_perm(uh0.x, uh1.x, 0x5410);
            Bhs[kp][c4 + 1] = __byte_perm(uh0.x, uh1.x, 0x7632);
            Bhs[kp][c4 + 2] = __byte_perm(uh0.y, uh1.y, 0x5410);
            Bhs[kp][c4 + 3] = __byte_perm(uh0.y, uh1.y, 0x7632);
            Bls[kp][c4 + 0] = __byte_perm(ul0.x, ul1.x, 0x5410);
            Bls[kp][c4 + 1] = __byte_perm(ul0.x, ul1.x, 0x7632);
            Bls[kp][c4 + 2] = __byte_perm(ul0.y, ul1.y, 0x5410);
            Bls[kp][c4 + 3] = __byte_perm(ul0.y, ul1.y, 0x7632);
        }
        __syncthreads();

        #pragma unroll
        for (int s = 0; s < 2; s++) {
            const int kb = s * 8;
            uint32_t ah[2][4], al[2][4];
            #pragma unroll
            for (int mt = 0; mt < 2; mt++) {
                int rr = wm + mt * 16 + g;
                ah[mt][0] = Ahs[kb + tg    ][rr    ];  al[mt][0] = Als[kb + tg    ][rr    ];
                ah[mt][1] = Ahs[kb + tg    ][rr + 8];  al[mt][1] = Als[kb + tg    ][rr + 8];
                ah[mt][2] = Ahs[kb + tg + 4][rr    ];  al[mt][2] = Als[kb + tg + 4][rr    ];
                ah[mt][3] = Ahs[kb + tg + 4][rr + 8];  al[mt][3] = Als[kb + tg + 4][rr + 8];
            }
            #pragma unroll
            for (int nt = 0; nt < 4; nt++) {
                int cc = wn + nt * 8 + g;
                uint32_t bh0 = Bhs[kb + tg    ][cc];
                uint32_t bh1 = Bhs[kb + tg + 4][cc];
                uint32_t bl0 = Bls[kb + tg    ][cc];
                uint32_t bl1 = Bls[kb + tg + 4][cc];
                #pragma unroll
                for (int mt = 0; mt < 2; mt++) {
                    MMA_F16(acc[mt][nt][0], acc[mt][nt][1], acc[mt][nt][2], acc[mt][nt][3],
                            al[mt][0], al[mt][1], al[mt][2], al[mt][3], bh0, bh1);
                    MMA_F16(acc[mt][nt][0], acc[mt][nt][1], acc[mt][nt][2], acc[mt][nt][3],
                            ah[mt][0], ah[mt][1], ah[mt][2], ah[mt][3], bl0, bl1);
                    MMA_F16(acc[mt][nt][0], acc[mt][nt][1], acc[mt][nt][2], acc[mt][nt][3],
                            ah[mt][0], ah[mt][1], ah[mt][2], ah[mt][3], bh0, bh1);
                }
            }
        }
        __syncthreads();
    }

    // epilogue: add bias, split to hi/lo fp16 planes
    #pragma unroll
    for (int mt = 0; mt < 2; mt++) {
        int r0 = wm + mt * 16 + g;
        float b0v = bsh[r0], b1v = bsh[r0 + 8];
        #pragma unroll
        for (int nt = 0; nt < 4; nt++) {
            int col = p0 + wn + nt * 8 + 2 * tg;
            float v00 = acc[mt][nt][0] + b0v, v01 = acc[mt][nt][1] + b0v;
            float v10 = acc[mt][nt][2] + b1v, v11 = acc[mt][nt][3] + b1v;
            __half h00, l00, h01, l01, h10, l10, h11, l11;
            split1(v00, h00, l00); split1(v01, h01, l01);
            split1(v10, h10, l10); split1(v11, h11, l11);
            size_t o0 = (size_t)(m0 + r0    ) * PCOLS + col;
            size_t o1 = (size_t)(m0 + r0 + 8) * PCOLS + col;
            *(__half2*)(Ch + o0) = __halves2half2(h00, h01);
            *(__half2*)(Cl + o0) = __halves2half2(l00, l01);
            *(__half2*)(Ch + o1) = __halves2half2(h10, h11);
            *(__half2*)(Cl + o1) = __halves2half2(l10, l11);
        }
    }
}

// ---------------------------------------------------------------------------
// Kernel 3: VN leaky-relu on planes. p from (Ph,Pl) for c<128 (or Pp==null),
// pooled vector Pp for c>=128. Output overwrites (Dh,Dl). 8 cols per thread.
// ---------------------------------------------------------------------------
__global__ __launch_bounds__(256)
void vn_lrelu_h(const __half* __restrict__ Ph, const __half* __restrict__ Pl,
                const float* __restrict__ Pp,
                __half* __restrict__ Dh, __half* __restrict__ Dl, float slope)
{
    int idx = blockIdx.x * 256 + threadIdx.x;   // c * 1024 + r
    int c  = idx >> 10;
    int r  = idx & 1023;
    int b  = r >> 7;
    int n8 = (r & 127) << 3;
    size_t base = (size_t)c * PCOLS + (size_t)b * 3072 + n8;

    float D0[8], D1[8], D2[8];
    ld8(Dh + base,        Dl + base,        D0);
    ld8(Dh + base + 1024, Dl + base + 1024, D1);
    ld8(Dh + base + 2048, Dl + base + 2048, D2);

    float P0[8], P1[8], P2[8];
    if (Pp != nullptr && c >= 128) {
        float v0 = Pp[(c - 128) * 24 + b * 3 + 0];
        float v1 = Pp[(c - 128) * 24 + b * 3 + 1];
        float v2 = Pp[(c - 128) * 24 + b * 3 + 2];
        #pragma unroll
        for (int j = 0; j < 8; j++) { P0[j] = v0; P1[j] = v1; P2[j] = v2; }
    } else {
        ld8(Ph + base,        Pl + base,        P0);
        ld8(Ph + base + 1024, Pl + base + 1024, P1);
        ld8(Ph + base + 2048, Pl + base + 2048, P2);
    }

    float O0[8], O1[8], O2[8];
    const float om = 1.f - slope;
    #pragma unroll
    for (int j = 0; j < 8; j++) {
        float dot = P0[j] * D0[j] + P1[j] * D1[j] + P2[j] * D2[j];
        float dsq = D0[j] * D0[j] + D1[j] * D1[j] + D2[j] * D2[j];
        float f   = dot / (dsq + EPS_);
        bool  pos = (dot >= 0.f);
        O0[j] = slope * P0[j] + om * (pos ? P0[j] : P0[j] - f * D0[j]);
        O1[j] = slope * P1[j] + om * (pos ? P1[j] : P1[j] - f * D1[j]);
        O2[j] = slope * P2[j] + om * (pos ? P2[j] : P2[j] - f * D2[j]);
    }
    st8(O0, Dh + base,        Dl + base);
    st8(O1, Dh + base + 1024, Dl + base + 1024);
    st8(O2, Dh + base + 2048, Dl + base + 2048);
}

// ---------------------------------------------------------------------------
// Kernel 4: h = xs + dx -> H0 planes (unless last) ; pooled -> P128[c][bd]
// one block per (c, bd); 128 threads x 8 cols
// ---------------------------------------------------------------------------
__global__ __launch_bounds__(128)
void addpool_h(const __half* __restrict__ Xh, const __half* __restrict__ Xl,
               const __half* __restrict__ Dxh, const __half* __restrict__ Dxl,
               __half* __restrict__ Hh, __half* __restrict__ Hl,
               float* __restrict__ P, int last)
{
    __shared__ float red[4];
    int c  = blockIdx.x / 24;
    int bd = blockIdx.x % 24;
    size_t base = (size_t)c * PCOLS + (size_t)bd * 1024 + threadIdx.x * 8;

    float a[8], d[8], h[8];
    ld8(Xh + base,  Xl + base,  a);
    ld8(Dxh + base, Dxl + base, d);
    float s = 0.f;
    #pragma unroll
    for (int j = 0; j < 8; j++) { h[j] = a[j] + d[j]; s += h[j]; }
    if (!last) st8(h, Hh + base, Hl + base);

    #pragma unroll
    for (int o = 16; o; o >>= 1) s += __shfl_down_sync(0xffffffffu, s, o);
    if ((threadIdx.x & 31) == 0) red[threadIdx.x >> 5] = s;
    __syncthreads();
    if (threadIdx.x == 0)
        P[c * 24 + bd] = (red[0] + red[1] + red[2] + red[3]) * (1.f / N_);
}

// ---------------------------------------------------------------------------
// Kernel 5: bias[m][bd] = sum_c W[m][128+c] * P[c][bd]   (fp32 weights)
// ---------------------------------------------------------------------------
__global__ void bias_k(const float* __restrict__ W, int lda,
                       const float* __restrict__ P, float* __restrict__ out)
{
    int m = blockIdx.x, bd = threadIdx.x;   // 24 threads
    float s = 0.f;
    #pragma unroll 8
    for (int c = 0; c < 128; c++)
        s += W[(size_t)m * lda + 128 + c] * P[c * 24 + bd];
    out[m * 24 + bd] = s;
}

// ---------------------------------------------------------------------------
// Kernel 6: head (fp32, tiny)
// ---------------------------------------------------------------------------
__global__ __launch_bounds__(128)
void head_kernel(const float* __restrict__ P, const float* __restrict__ Wd,
                 const float* __restrict__ Wc, float* __restrict__ out)
{
    __shared__ float hid[H_][3];
    __shared__ float act[H_][3];
    const int b = blockIdx.x, h = threadIdx.x;

    hid[h][0] = P[h * 24 + b * 3 + 0];
    hid[h][1] = P[h * 24 + b * 3 + 1];
    hid[h][2] = P[h * 24 + b * 3 + 2];
    __syncthreads();

    float d0 = 0.f, d1 = 0.f, d2 = 0.f;
    #pragma unroll 8
    for (int c = 0; c < H_; c++) {
        float w = Wd[h * H_ + c];
        d0 = fmaf(w, hid[c][0], d0);
        d1 = fmaf(w, hid[c][1], d1);
        d2 = fmaf(w, hid[c][2], d2);
    }
    float p0 = hid[h][0], p1 = hid[h][1], p2 = hid[h][2];
    float dot = p0 * d0 + p1 * d1 + p2 * d2;
    float dsq = d0 * d0 + d1 * d1 + d2 * d2;
    float f   = dot / (dsq + EPS_);
    bool  pos = (dot >= 0.f);
    act[h][0] = 0.2f * p0 + 0.8f * (pos ? p0 : p0 - f * d0);
    act[h][1] = 0.2f * p1 + 0.8f * (pos ? p1 : p1 - f * d1);
    act[h][2] = 0.2f * p2 + 0.8f * (pos ? p2 : p2 - f * d2);
    __syncthreads();

    float o0 = 0.f, o1 = 0.f, o2 = 0.f;
    #pragma unroll 8
    for (int c = 0; c < H_; c++) {
        float w = Wc[h * H_ + c];
        o0 = fmaf(w, act[c][0], o0);
        o1 = fmaf(w, act[c][1], o1);
        o2 = fmaf(w, act[c][2], o2);
    }
    out[b * (H_ * 3) + h * 3 + 0] = o0;
    out[b * (H_ * 3) + h * 3 + 1] = o1;
    out[b * (H_ * 3) + h * 3 + 2] = o2;
}

// ---------------------------------------------------------------------------
// launcher
// ---------------------------------------------------------------------------
extern "C" void kernel_launch(void* const* d_in, const int* in_sizes, int n_in,
                              void* d_out, int out_size)
{
    const float* x       = (const float*)d_in[0];
    const float* cpWf    = (const float*)d_in[1];
    const float* cpWd    = (const float*)d_in[2];
    const float* fcposW  = (const float*)d_in[3];   // (256,128)
    const float* blkWd0  = (const float*)d_in[4];   // (4,256,256)
    const float* blkW0   = (const float*)d_in[5];   // (4,128,256)
    const float* blkWd1  = (const float*)d_in[6];   // (4,128,128)
    const float* blkW1   = (const float*)d_in[7];   // (4,128,128)
    const float* blkWs   = (const float*)d_in[8];   // (4,128,256)
    const float* actWd   = (const float*)d_in[9];
    const float* fccW    = (const float*)d_in[10];
    float* out = (float*)d_out;

    __half *H0h, *H0l, *T0h, *T0l, *T1h, *T1l, *T2h, *T2l, *T3h, *T3l, *T4h, *T4l;
    __half *Wh, *Wl;
    float *P128, *bWd0, *bWs;
    cudaGetSymbolAddress((void**)&H0h, g_H0h); cudaGetSymbolAddress((void**)&H0l, g_H0l);
    cudaGetSymbolAddress((void**)&T0h, g_T0h); cudaGetSymbolAddress((void**)&T0l, g_T0l);
    cudaGetSymbolAddress((void**)&T1h, g_T1h); cudaGetSymbolAddress((void**)&T1l, g_T1l);
    cudaGetSymbolAddress((void**)&T2h, g_T2h); cudaGetSymbolAddress((void**)&T2l, g_T2l);
    cudaGetSymbolAddress((void**)&T3h, g_T3h); cudaGetSymbolAddress((void**)&T3l, g_T3l);
    cudaGetSymbolAddress((void**)&T4h, g_T4h); cudaGetSymbolAddress((void**)&T4l, g_T4l);
    cudaGetSymbolAddress((void**)&Wh,  g_Wh);  cudaGetSymbolAddress((void**)&Wl,  g_Wl);
    cudaGetSymbolAddress((void**)&P128, g_P128);
    cudaGetSymbolAddress((void**)&bWd0, g_bWd0);
    cudaGetSymbolAddress((void**)&bWs,  g_bWs);

    // pre-split all GEMM weights (runs concurrently with knn)
    convw_kernel<<<(32768  + 255) / 256, 256>>>(fcposW, Wh + OFF_FCPOS, Wl + OFF_FCPOS, 32768);
    convw_kernel<<<(262144 + 255) / 256, 256>>>(blkWd0, Wh + OFF_WD0,   Wl + OFF_WD0,   262144);
    convw_kernel<<<(131072 + 255) / 256, 256>>>(blkW0,  Wh + OFF_W0,    Wl + OFF_W0,    131072);
    convw_kernel<<<(65536  + 255) / 256, 256>>>(blkWd1, Wh + OFF_WD1,   Wl + OFF_WD1,   65536);
    convw_kernel<<<(65536  + 255) / 256, 256>>>(blkW1,  Wh + OFF_W1,    Wl + OFF_W1,    65536);
    convw_kernel<<<(131072 + 255) / 256, 256>>>(blkWs,  Wh + OFF_WS,    Wl + OFF_WS,    131072);

    const int NT = PCOLS / 64;   // 384 column tiles

    // stage A: knn + feature + conv_pos + mean_k -> T1 planes (128 x P)
    knn_conv_kernel<<<B_ * N_, 128>>>(x, cpWf, cpWd, T1h, T1l);

    // fc_pos: H0 (256 x P) = fc_pos_W @ T1
    gemm_f16x3<<<dim3(NT, 2), 256>>>(Wh + OFF_FCPOS, Wl + OFF_FCPOS, 128,
                                     T1h, T1l, H0h, H0l, 128, nullptr);

    for (int i = 0; i < 4; i++) {
        const __half* Wd0h = Wh + OFF_WD0 + (size_t)i * 65536;
        const __half* Wd0l = Wl + OFF_WD0 + (size_t)i * 65536;
        const __half* W0h  = Wh + OFF_W0  + (size_t)i * 32768;
        const __half* W0l  = Wl + OFF_W0  + (size_t)i * 32768;
        const __half* Wd1h = Wh + OFF_WD1 + (size_t)i * 16384;
        const __half* Wd1l = Wl + OFF_WD1 + (size_t)i * 16384;
        const __half* W1h  = Wh + OFF_W1  + (size_t)i * 16384;
        const __half* W1l  = Wl + OFF_W1  + (size_t)i * 16384;
        const __half* Wsh  = Wh + OFF_WS  + (size_t)i * 32768;
        const __half* Wsl  = Wl + OFF_WS  + (size_t)i * 32768;
        const int Kin    = (i == 0) ? 256 : 128;
        const float* bd0 = (i == 0) ? nullptr : bWd0;
        const float* bs  = (i == 0) ? nullptr : bWs;
        const float* Pp  = (i == 0) ? nullptr : P128;

        // d0 = Wd0 @ hidden ; a0 = lrelu(hidden, d0, 0) in T0 (256 x P)
        gemm_f16x3<<<dim3(NT, 2), 256>>>(Wd0h, Wd0l, 256, H0h, H0l, T0h, T0l, Kin, bd0);
        vn_lrelu_h<<<1024, 256>>>(H0h, H0l, Pp, T0h, T0l, 0.0f);

        // net = W0 @ a0 (128 x P)
        gemm_f16x3<<<dim3(NT, 1), 256>>>(W0h, W0l, 256, T0h, T0l, T1h, T1l, 256, nullptr);

        // d1 = Wd1 @ net ; a1 = lrelu(net, d1, 0) in T2
        gemm_f16x3<<<dim3(NT, 1), 256>>>(Wd1h, Wd1l, 128, T1h, T1l, T2h, T2l, 128, nullptr);
        vn_lrelu_h<<<512, 256>>>(T1h, T1l, nullptr, T2h, T2l, 0.0f);

        // dx = W1 @ a1 ; xs = Ws @ hidden
        gemm_f16x3<<<dim3(NT, 1), 256>>>(W1h, W1l, 128, T2h, T2l, T3h, T3l, 128, nullptr);
        gemm_f16x3<<<dim3(NT, 1), 256>>>(Wsh, Wsl, 256, H0h, H0l, T4h, T4l, Kin, bs);

        // h = xs + dx -> H0 planes ; pooled -> P128
        addpool_h<<<H_ * 24, 128>>>(T4h, T4l, T3h, T3l, H0h, H0l, P128, (i == 3) ? 1 : 0);

        // fold pooled half of next layer's Wd0/Ws into bias vectors
        if (i < 3) {
            bias_k<<<256, 24>>>(blkWd0 + (size_t)(i + 1) * 256 * 256, 256, P128, bWd0);
            bias_k<<<128, 24>>>(blkWs  + (size_t)(i + 1) * 128 * 256, 256, P128, bWs);
        }
    }

    head_kernel<<<B_, 128>>>(P128, actWd, fccW, out);

    (void)in_sizes; (void)n_in; (void)out_size;
}

// round 8
// speedup vs baseline: 2.4359x; 1.0195x over previous
#include <cuda_runtime.h>
#include <cuda_fp16.h>
#include <math_constants.h>
#include <cstdint>

// ---------------------------------------------------------------------------
// VN_Resnet_Encoder — B=8, N=1024, k=20, H=128, LAYER_NUM=4
// Column layout: col = (b*3 + d)*1024 + n,  P = 24576
// Split-fp16 (hi+lo) storage everywhere; mma.m16n8k16 x3 GEMMs.
// 3-plane batched GEMM blocks with fused VN-relu / bias / residual epilogues.
// ---------------------------------------------------------------------------

#define B_      8
#define N_      1024
#define KNN_    20
#define H_      128
#define PCOLS   24576
#define EPS_    1e-6f

// ---------------- scratch (static device globals; no allocation) -----------
__device__ __half g_H0h[256 * PCOLS], g_H0l[256 * PCOLS];
__device__ __half g_T0h[256 * PCOLS], g_T0l[256 * PCOLS];
__device__ __half g_T1h[128 * PCOLS], g_T1l[128 * PCOLS];
__device__ __half g_T2h[128 * PCOLS], g_T2l[128 * PCOLS];
__device__ __half g_T4h[128 * PCOLS], g_T4l[128 * PCOLS];
__device__ float  g_P128[H_ * 24];
__device__ float  g_bWd0[256 * 24];
__device__ float  g_bWs [128 * 24];

// pre-split weight pool (fp16 hi/lo planes)
#define OFF_FCPOS 0                       // 256x128
#define OFF_MRG   32768                   // L0: 384x256 ; L1-3: 384x128
#define OFF_MRG1  131072
#define OFF_W0    278528                  // 4 x 128x256
#define OFF_WD1   409600                  // 4 x 128x128
#define OFF_W1    475136                  // 4 x 128x128
#define WPOOL     540672
__device__ __half g_Wh[WPOOL], g_Wl[WPOOL];

// ---------------- helpers ---------------------------------------------------
__device__ __forceinline__ void split1(float v, __half& hi, __half& lo) {
    hi = __float2half_rn(v);
    lo = __float2half_rn(v - __half2float(hi));
}

__device__ __forceinline__ void ld8(const __half* ph, const __half* pl, float* out) {
    uint4 uh = *(const uint4*)ph;
    uint4 ul = *(const uint4*)pl;
    const __half2* hh = (const __half2*)&uh;
    const __half2* ll = (const __half2*)&ul;
    #pragma unroll
    for (int j = 0; j < 4; j++) {
        float2 fh = __half22float2(hh[j]);
        float2 fl = __half22float2(ll[j]);
        out[2 * j]     = fh.x + fl.x;
        out[2 * j + 1] = fh.y + fl.y;
    }
}

// ---------------------------------------------------------------------------
// Kernel 0a: split fp32 weights -> fp16 hi/lo pool
// ---------------------------------------------------------------------------
__global__ void convw_kernel(const float* __restrict__ src,
                             __half* __restrict__ dh, __half* __restrict__ dl, int n)
{
    int i = blockIdx.x * 256 + threadIdx.x;
    if (i >= n) return;
    __half hi, lo;
    split1(src[i], hi, lo);
    dh[i] = hi; dl[i] = lo;
}

// Kernel 0b: repack merged [Wd0(256 rows); Ws(128 rows)] taking first Kin cols
__global__ void repack_merged(const float* __restrict__ Wd0,
                              const float* __restrict__ Ws, int Kin,
                              __half* __restrict__ dh, __half* __restrict__ dl)
{
    int i = blockIdx.x * 256 + threadIdx.x;
    if (i >= 384 * Kin) return;
    int r = i / Kin, c = i - r * Kin;
    float v = (r < 256) ? Wd0[r * 256 + c] : Ws[(r - 256) * 256 + c];
    __half hi, lo;
    split1(v, hi, lo);
    dh[i] = hi; dl[i] = lo;
}

// ---------------------------------------------------------------------------
// Kernel 1: KNN + graph feature cross + conv_pos + mean_k  (writes T1 planes)
// ---------------------------------------------------------------------------
__global__ __launch_bounds__(128)
void knn_conv_kernel(const float* __restrict__ x,
                     const float* __restrict__ Wf,
                     const float* __restrict__ Wd,
                     __half* __restrict__ Oh, __half* __restrict__ Ol)
{
    __shared__ float px[N_], py[N_], pz[N_];
    __shared__ float sc[N_];
    __shared__ int   nb[KNN_];
    __shared__ float wmax[4];
    __shared__ int   warg[4];

    const int b = blockIdx.x >> 10;
    const int n = blockIdx.x & 1023;
    const float* xb = x + (size_t)b * N_ * 3;

    for (int i = threadIdx.x; i < N_; i += 128) {
        px[i] = xb[i * 3 + 0];
        py[i] = xb[i * 3 + 1];
        pz[i] = xb[i * 3 + 2];
    }
    __syncthreads();

    const float cx = px[n], cy = py[n], cz = pz[n];

    for (int i = threadIdx.x; i < N_; i += 128) {
        float dx = px[i] - cx, dy = py[i] - cy, dz = pz[i] - cz;
        sc[i] = -(dx * dx + dy * dy + dz * dz);
    }
    __syncthreads();

    const int lane = threadIdx.x & 31, wrp = threadIdx.x >> 5;

    for (int kk = 0; kk < KNN_; kk++) {
        float best = -CUDART_INF_F;
        int   bi   = 1 << 30;
        for (int i = threadIdx.x; i < N_; i += 128) {
            float s = sc[i];
            if (s > best || (s == best && i < bi)) { best = s; bi = i; }
        }
        #pragma unroll
        for (int o = 16; o; o >>= 1) {
            float ob = __shfl_down_sync(0xffffffffu, best, o);
            int   oi = __shfl_down_sync(0xffffffffu, bi,   o);
            if (ob > best || (ob == best && oi < bi)) { best = ob; bi = oi; }
        }
        if (lane == 0) { wmax[wrp] = best; warg[wrp] = bi; }
        __syncthreads();
        if (threadIdx.x == 0) {
            float bb = wmax[0]; int ii = warg[0];
            #pragma unroll
            for (int w = 1; w < 4; w++)
                if (wmax[w] > bb || (wmax[w] == bb && warg[w] < ii)) { bb = wmax[w]; ii = warg[w]; }
            nb[kk] = ii;
            sc[ii] = -CUDART_INF_F;
        }
        __syncthreads();
    }

    const int h = threadIdx.x;
    const float wf0 = Wf[h * 3 + 0], wf1 = Wf[h * 3 + 1], wf2 = Wf[h * 3 + 2];
    const float wd0 = Wd[h * 3 + 0], wd1 = Wd[h * 3 + 1], wd2 = Wd[h * 3 + 2];

    float a0 = 0.f, a1 = 0.f, a2 = 0.f;
    #pragma unroll 4
    for (int kk = 0; kk < KNN_; kk++) {
        int j = nb[kk];
        float nx = px[j], ny = py[j], nz = pz[j];
        float e0 = nx - cx, e1 = ny - cy, e2 = nz - cz;
        float r0 = ny * cz - nz * cy;
        float r1 = nz * cx - nx * cz;
        float r2 = nx * cy - ny * cx;

        float pd0 = wf0 * e0 + wf1 * cx + wf2 * r0;
        float pd1 = wf0 * e1 + wf1 * cy + wf2 * r1;
        float pd2 = wf0 * e2 + wf1 * cz + wf2 * r2;
        float dd0 = wd0 * e0 + wd1 * cx + wd2 * r0;
        float dd1 = wd0 * e1 + wd1 * cy + wd2 * r1;
        float dd2 = wd0 * e2 + wd1 * cz + wd2 * r2;

        float dot = pd0 * dd0 + pd1 * dd1 + pd2 * dd2;
        float dsq = dd0 * dd0 + dd1 * dd1 + dd2 * dd2;
        float f   = dot / (dsq + EPS_);
        bool  pos = (dot >= 0.f);
        a0 += 0.2f * pd0 + 0.8f * (pos ? pd0 : pd0 - f * dd0);
        a1 += 0.2f * pd1 + 0.8f * (pos ? pd1 : pd1 - f * dd1);
        a2 += 0.2f * pd2 + 0.8f * (pos ? pd2 : pd2 - f * dd2);
    }

    size_t base = (size_t)h * PCOLS + (size_t)b * 3 * N_ + n;
    __half hi, lo;
    split1(a0 * (1.0f / KNN_), hi, lo); Oh[base         ] = hi; Ol[base         ] = lo;
    split1(a1 * (1.0f / KNN_), hi, lo); Oh[base + N_    ] = hi; Ol[base + N_    ] = lo;
    split1(a2 * (1.0f / KNN_), hi, lo); Oh[base + 2 * N_] = hi; Ol[base + 2 * N_] = lo;
}

// ---------------------------------------------------------------------------
// Kernel 2: 3-plane batched split-fp16 x3 tensor-core GEMM.
// One block: 128(m) x 64(n) x 3 spatial planes (cols +0/+1024/+2048).
// MODE 0: plain (+bias1 optional) -> Ch/Cl
// MODE 1: rows < 256: bias1 + VN-relu(p from Ph/Pl or Pp for rows>=128) -> Ch/Cl
//         rows >= 256: +bias2 -> C2h/C2l (row - 256)
// MODE 2: + A2 (residual) -> Ch/Cl
// ---------------------------------------------------------------------------
#define MMA_F16(c0,c1,c2,c3,a0,a1,a2,a3,b0,b1)                               \
    asm volatile("mma.sync.aligned.m16n8k16.row.col.f32.f16.f16.f32 "        \
        "{%0,%1,%2,%3},{%4,%5,%6,%7},{%8,%9},{%0,%1,%2,%3};"                 \
        : "+f"(c0),"+f"(c1),"+f"(c2),"+f"(c3)                                \
        : "r"(a0),"r"(a1),"r"(a2),"r"(a3),"r"(b0),"r"(b1))

template<int MODE>
__global__ __launch_bounds__(256)
void gemm3p(const __half* __restrict__ Wh_, const __half* __restrict__ Wl_, int lda,
            const __half* __restrict__ Xh, const __half* __restrict__ Xl,
            __half* __restrict__ Ch, __half* __restrict__ Cl,
            __half* __restrict__ C2h, __half* __restrict__ C2l,
            const __half* __restrict__ Ph, const __half* __restrict__ Pl,
            const float* __restrict__ Pp,
            const float* __restrict__ bias1, const float* __restrict__ bias2,
            const __half* __restrict__ A2h, const __half* __restrict__ A2l,
            int K)
{
    __shared__ uint32_t Ahs[16][136];
    __shared__ uint32_t Als[16][136];
    __shared__ uint32_t Bhs[3][16][72];
    __shared__ uint32_t Bls[3][16][72];

    const int t     = threadIdx.x;
    const int q     = blockIdx.x;          // 0..127
    const int bb    = q >> 4;
    const int ntile = q & 15;
    const int bcol  = bb * 3072 + ntile * 64;
    const int bd0   = bb * 3;
    const int m0    = blockIdx.y * 128;
    const int warp  = t >> 5, lane = t & 31;
    const int wm    = (warp & 3) * 32;
    const int wn    = (warp >> 2) * 32;
    const int g     = lane >> 2, tg = lane & 3;

    float acc[3][2][4][4];
    #pragma unroll
    for (int p = 0; p < 3; p++)
        #pragma unroll
        for (int i = 0; i < 2; i++)
            #pragma unroll
            for (int j = 0; j < 4; j++)
                #pragma unroll
                for (int l = 0; l < 4; l++) acc[p][i][j][l] = 0.f;

    for (int k0 = 0; k0 < K; k0 += 32) {
        // stage A (128 x 32): copy pre-split fp16, layout half2{k,k+1} at [k2][m]
        #pragma unroll
        for (int i = 0; i < 2; i++) {
            int idx = t + i * 256;
            int m   = idx >> 2;
            int oct = idx & 3;
            const size_t go = (size_t)(m0 + m) * lda + k0 + oct * 8;
            uint4 vh = *(const uint4*)(Wh_ + go);
            uint4 vl = *(const uint4*)(Wl_ + go);
            int k2 = oct * 4;
            Ahs[k2 + 0][m] = vh.x; Ahs[k2 + 1][m] = vh.y;
            Ahs[k2 + 2][m] = vh.z; Ahs[k2 + 3][m] = vh.w;
            Als[k2 + 0][m] = vl.x; Als[k2 + 1][m] = vl.y;
            Als[k2 + 2][m] = vl.z; Als[k2 + 3][m] = vl.w;
        }
        // stage B: 3 planes of (32 x 64), interleave k-pairs into half2
        #pragma unroll
        for (int p = 0; p < 3; p++) {
            int kp = t >> 4;
            int cg = t & 15;
            const size_t go = (size_t)(k0 + 2 * kp) * PCOLS + bcol + p * 1024 + cg * 4;
            uint2 uh0 = *(const uint2*)(Xh + go);
            uint2 uh1 = *(const uint2*)(Xh + go + PCOLS);
            uint2 ul0 = *(const uint2*)(Xl + go);
            uint2 ul1 = *(const uint2*)(Xl + go + PCOLS);
            int c4 = cg * 4;
            Bhs[p][kp][c4 + 0] = __byte_perm(uh0.x, uh1.x, 0x5410);
            Bhs[p][kp][c4 + 1] = __byte_perm(uh0.x, uh1.x, 0x7632);
            Bhs[p][kp][c4 + 2] = __byte_perm(uh0.y, uh1.y, 0x5410);
            Bhs[p][kp][c4 + 3] = __byte_perm(uh0.y, uh1.y, 0x7632);
            Bls[p][kp][c4 + 0] = __byte_perm(ul0.x, ul1.x, 0x5410);
            Bls[p][kp][c4 + 1] = __byte_perm(ul0.x, ul1.x, 0x7632);
            Bls[p][kp][c4 + 2] = __byte_perm(ul0.y, ul1.y, 0x5410);
            Bls[p][kp][c4 + 3] = __byte_perm(ul0.y, ul1.y, 0x7632);
        }
        __syncthreads();

        #pragma unroll
        for (int s = 0; s < 2; s++) {
            const int kb = s * 8;
            uint32_t ah[2][4], al[2][4];
            #pragma unroll
            for (int mt = 0; mt < 2; mt++) {
                int rr = wm + mt * 16 + g;
                ah[mt][0] = Ahs[kb + tg    ][rr    ];  al[mt][0] = Als[kb + tg    ][rr    ];
                ah[mt][1] = Ahs[kb + tg    ][rr + 8];  al[mt][1] = Als[kb + tg    ][rr + 8];
                ah[mt][2] = Ahs[kb + tg + 4][rr    ];  al[mt][2] = Als[kb + tg + 4][rr    ];
                ah[mt][3] = Ahs[kb + tg + 4][rr + 8];  al[mt][3] = Als[kb + tg + 4][rr + 8];
            }
            #pragma unroll
            for (int p = 0; p < 3; p++) {
                #pragma unroll
                for (int nt = 0; nt < 4; nt++) {
                    int cc = wn + nt * 8 + g;
                    uint32_t bh0 = Bhs[p][kb + tg    ][cc];
                    uint32_t bh1 = Bhs[p][kb + tg + 4][cc];
                    uint32_t bl0 = Bls[p][kb + tg    ][cc];
                    uint32_t bl1 = Bls[p][kb + tg + 4][cc];
                    #pragma unroll
                    for (int mt = 0; mt < 2; mt++) {
                        MMA_F16(acc[p][mt][nt][0], acc[p][mt][nt][1], acc[p][mt][nt][2], acc[p][mt][nt][3],
                                al[mt][0], al[mt][1], al[mt][2], al[mt][3], bh0, bh1);
                        MMA_F16(acc[p][mt][nt][0], acc[p][mt][nt][1], acc[p][mt][nt][2], acc[p][mt][nt][3],
                                ah[mt][0], ah[mt][1], ah[mt][2], ah[mt][3], bl0, bl1);
                        MMA_F16(acc[p][mt][nt][0], acc[p][mt][nt][1], acc[p][mt][nt][2], acc[p][mt][nt][3],
                                ah[mt][0], ah[mt][1], ah[mt][2], ah[mt][3], bh0, bh1);
                    }
                }
            }
        }
        __syncthreads();
    }

    // -------------------- epilogue --------------------
    #pragma unroll
    for (int mt = 0; mt < 2; mt++) {
        #pragma unroll
        for (int ri = 0; ri < 2; ri++) {
            const int rabs = m0 + wm + mt * 16 + g + ri * 8;
            #pragma unroll
            for (int nt = 0; nt < 4; nt++) {
                const int col = bcol + wn + nt * 8 + 2 * tg;
                float vx[3], vy[3];
                #pragma unroll
                for (int d = 0; d < 3; d++) {
                    vx[d] = acc[d][mt][nt][2 * ri + 0];
                    vy[d] = acc[d][mt][nt][2 * ri + 1];
                }

                if (MODE == 0) {
                    #pragma unroll
                    for (int d = 0; d < 3; d++) {
                        float bv = bias1 ? bias1[rabs * 24 + bd0 + d] : 0.f;
                        float ox = vx[d] + bv, oy = vy[d] + bv;
                        size_t o = (size_t)rabs * PCOLS + col + d * 1024;
                        __half hx, lx, hy, ly;
                        split1(ox, hx, lx); split1(oy, hy, ly);
                        *(__half2*)(Ch + o) = __halves2half2(hx, hy);
                        *(__half2*)(Cl + o) = __halves2half2(lx, ly);
                    }
                } else if (MODE == 1) {
                    if (rabs < 256) {
                        if (bias1) {
                            #pragma unroll
                            for (int d = 0; d < 3; d++) {
                                float bv = bias1[rabs * 24 + bd0 + d];
                                vx[d] += bv; vy[d] += bv;
                            }
                        }
                        float pxv[3], pyv[3];
                        if (Pp != nullptr && rabs >= 128) {
                            #pragma unroll
                            for (int d = 0; d < 3; d++) {
                                float pv = Pp[(rabs - 128) * 24 + bd0 + d];
                                pxv[d] = pv; pyv[d] = pv;
                            }
                        } else {
                            #pragma unroll
                            for (int d = 0; d < 3; d++) {
                                size_t o = (size_t)rabs * PCOLS + col + d * 1024;
                                float2 fh = __half22float2(*(const __half2*)(Ph + o));
                                float2 fl = __half22float2(*(const __half2*)(Pl + o));
                                pxv[d] = fh.x + fl.x; pyv[d] = fh.y + fl.y;
                            }
                        }
                        float dotx = 0.f, dsqx = 0.f, doty = 0.f, dsqy = 0.f;
                        #pragma unroll
                        for (int d = 0; d < 3; d++) {
                            dotx += pxv[d] * vx[d]; dsqx += vx[d] * vx[d];
                            doty += pyv[d] * vy[d]; dsqy += vy[d] * vy[d];
                        }
                        float fx = dotx / (dsqx + EPS_), fy = doty / (dsqy + EPS_);
                        bool posx = (dotx >= 0.f), posy = (doty >= 0.f);
                        #pragma unroll
                        for (int d = 0; d < 3; d++) {
                            float ox = posx ? pxv[d] : pxv[d] - fx * vx[d];
                            float oy = posy ? pyv[d] : pyv[d] - fy * vy[d];
                            size_t o = (size_t)rabs * PCOLS + col + d * 1024;
                            __half hx, lx, hy, ly;
                            split1(ox, hx, lx); split1(oy, hy, ly);
                            *(__half2*)(Ch + o) = __halves2half2(hx, hy);
                            *(__half2*)(Cl + o) = __halves2half2(lx, ly);
                        }
                    } else {
                        const int rr = rabs - 256;
                        #pragma unroll
                        for (int d = 0; d < 3; d++) {
                            float bv = bias2 ? bias2[rr * 24 + bd0 + d] : 0.f;
                            float ox = vx[d] + bv, oy = vy[d] + bv;
                            size_t o = (size_t)rr * PCOLS + col + d * 1024;
                            __half hx, lx, hy, ly;
                            split1(ox, hx, lx); split1(oy, hy, ly);
                            *(__half2*)(C2h + o) = __halves2half2(hx, hy);
                            *(__half2*)(C2l + o) = __halves2half2(lx, ly);
                        }
                    }
                } else { // MODE == 2 : residual add
                    #pragma unroll
                    for (int d = 0; d < 3; d++) {
                        size_t o = (size_t)rabs * PCOLS + col + d * 1024;
                        float2 fh = __half22float2(*(const __half2*)(A2h + o));
                        float2 fl = __half22float2(*(const __half2*)(A2l + o));
                        float ox = vx[d] + fh.x + fl.x;
                        float oy = vy[d] + fh.y + fl.y;
                        __half hx, lx, hy, ly;
                        split1(ox, hx, lx); split1(oy, hy, ly);
                        *(__half2*)(Ch + o) = __halves2half2(hx, hy);
                        *(__half2*)(Cl + o) = __halves2half2(lx, ly);
                    }
                }
            }
        }
    }
}

// ---------------------------------------------------------------------------
// Kernel 3: pool-only. P128[c][bd] = mean_n H[c, bd*1024 + n]
// ---------------------------------------------------------------------------
__global__ __launch_bounds__(128)
void pool_h(const __half* __restrict__ Hh, const __half* __restrict__ Hl,
            float* __restrict__ P)
{
    __shared__ float red[4];
    int c  = blockIdx.x / 24;
    int bd = blockIdx.x % 24;
    size_t base = (size_t)c * PCOLS + (size_t)bd * 1024 + threadIdx.x * 8;
    float v[8];
    ld8(Hh + base, Hl + base, v);
    float s = 0.f;
    #pragma unroll
    for (int j = 0; j < 8; j++) s += v[j];
    #pragma unroll
    for (int o = 16; o; o >>= 1) s += __shfl_down_sync(0xffffffffu, s, o);
    if ((threadIdx.x & 31) == 0) red[threadIdx.x >> 5] = s;
    __syncthreads();
    if (threadIdx.x == 0)
        P[c * 24 + bd] = (red[0] + red[1] + red[2] + red[3]) * (1.f / N_);
}

// ---------------------------------------------------------------------------
// Kernel 4: bias[m][bd] = sum_c W[m][128+c] * P[c][bd]   (fp32 weights)
// ---------------------------------------------------------------------------
__global__ void bias_k(const float* __restrict__ W, int lda,
                       const float* __restrict__ P, float* __restrict__ out)
{
    int m = blockIdx.x, bd = threadIdx.x;   // 24 threads
    float s = 0.f;
    #pragma unroll 8
    for (int c = 0; c < 128; c++)
        s += W[(size_t)m * lda + 128 + c] * P[c * 24 + bd];
    out[m * 24 + bd] = s;
}

// ---------------------------------------------------------------------------
// Kernel 5: head (fp32, tiny)
// ---------------------------------------------------------------------------
__global__ __launch_bounds__(128)
void head_kernel(const float* __restrict__ P, const float* __restrict__ Wd,
                 const float* __restrict__ Wc, float* __restrict__ out)
{
    __shared__ float hid[H_][3];
    __shared__ float act[H_][3];
    const int b = blockIdx.x, h = threadIdx.x;

    hid[h][0] = P[h * 24 + b * 3 + 0];
    hid[h][1] = P[h * 24 + b * 3 + 1];
    hid[h][2] = P[h * 24 + b * 3 + 2];
    __syncthreads();

    float d0 = 0.f, d1 = 0.f, d2 = 0.f;
    #pragma unroll 8
    for (int c = 0; c < H_; c++) {
        float w = Wd[h * H_ + c];
        d0 = fmaf(w, hid[c][0], d0);
        d1 = fmaf(w, hid[c][1], d1);
        d2 = fmaf(w, hid[c][2], d2);
    }
    float p0 = hid[h][0], p1 = hid[h][1], p2 = hid[h][2];
    float dot = p0 * d0 + p1 * d1 + p2 * d2;
    float dsq = d0 * d0 + d1 * d1 + d2 * d2;
    float f   = dot / (dsq + EPS_);
    bool  pos = (dot >= 0.f);
    act[h][0] = 0.2f * p0 + 0.8f * (pos ? p0 : p0 - f * d0);
    act[h][1] = 0.2f * p1 + 0.8f * (pos ? p1 : p1 - f * d1);
    act[h][2] = 0.2f * p2 + 0.8f * (pos ? p2 : p2 - f * d2);
    __syncthreads();

    float o0 = 0.f, o1 = 0.f, o2 = 0.f;
    #pragma unroll 8
    for (int c = 0; c < H_; c++) {
        float w = Wc[h * H_ + c];
        o0 = fmaf(w, act[c][0], o0);
        o1 = fmaf(w, act[c][1], o1);
        o2 = fmaf(w, act[c][2], o2);
    }
    out[b * (H_ * 3) + h * 3 + 0] = o0;
    out[b * (H_ * 3) + h * 3 + 1] = o1;
    out[b * (H_ * 3) + h * 3 + 2] = o2;
}

// ---------------------------------------------------------------------------
// launcher
// ---------------------------------------------------------------------------
extern "C" void kernel_launch(void* const* d_in, const int* in_sizes, int n_in,
                              void* d_out, int out_size)
{
    const float* x       = (const float*)d_in[0];
    const float* cpWf    = (const float*)d_in[1];
    const float* cpWd    = (const float*)d_in[2];
    const float* fcposW  = (const float*)d_in[3];   // (256,128)
    const float* blkWd0  = (const float*)d_in[4];   // (4,256,256)
    const float* blkW0   = (const float*)d_in[5];   // (4,128,256)
    const float* blkWd1  = (const float*)d_in[6];   // (4,128,128)
    const float* blkW1   = (const float*)d_in[7];   // (4,128,128)
    const float* blkWs   = (const float*)d_in[8];   // (4,128,256)
    const float* actWd   = (const float*)d_in[9];
    const float* fccW    = (const float*)d_in[10];
    float* out = (float*)d_out;

    __half *H0h, *H0l, *T0h, *T0l, *T1h, *T1l, *T2h, *T2l, *T4h, *T4l, *Wh, *Wl;
    float *P128, *bWd0, *bWs;
    cudaGetSymbolAddress((void**)&H0h, g_H0h); cudaGetSymbolAddress((void**)&H0l, g_H0l);
    cudaGetSymbolAddress((void**)&T0h, g_T0h); cudaGetSymbolAddress((void**)&T0l, g_T0l);
    cudaGetSymbolAddress((void**)&T1h, g_T1h); cudaGetSymbolAddress((void**)&T1l, g_T1l);
    cudaGetSymbolAddress((void**)&T2h, g_T2h); cudaGetSymbolAddress((void**)&T2l, g_T2l);
    cudaGetSymbolAddress((void**)&T4h, g_T4h); cudaGetSymbolAddress((void**)&T4l, g_T4l);
    cudaGetSymbolAddress((void**)&Wh,  g_Wh);  cudaGetSymbolAddress((void**)&Wl,  g_Wl);
    cudaGetSymbolAddress((void**)&P128, g_P128);
    cudaGetSymbolAddress((void**)&bWd0, g_bWd0);
    cudaGetSymbolAddress((void**)&bWs,  g_bWs);

    // ---- weight conversion / packing ----
    convw_kernel<<<(32768 + 255) / 256, 256>>>(fcposW, Wh + OFF_FCPOS, Wl + OFF_FCPOS, 32768);
    // merged [Wd0;Ws]: layer0 Kin=256, layers1-3 Kin=128
    repack_merged<<<(384 * 256 + 255) / 256, 256>>>(blkWd0, blkWs, 256,
                                                    Wh + OFF_MRG, Wl + OFF_MRG);
    for (int i = 1; i < 4; i++) {
        repack_merged<<<(384 * 128 + 255) / 256, 256>>>(
            blkWd0 + (size_t)i * 256 * 256, blkWs + (size_t)i * 128 * 256, 128,
            Wh + OFF_MRG1 + (size_t)(i - 1) * 49152,
            Wl + OFF_MRG1 + (size_t)(i - 1) * 49152);
    }
    convw_kernel<<<(131072 + 255) / 256, 256>>>(blkW0,  Wh + OFF_W0,  Wl + OFF_W0,  131072);
    convw_kernel<<<(65536  + 255) / 256, 256>>>(blkWd1, Wh + OFF_WD1, Wl + OFF_WD1, 65536);
    convw_kernel<<<(65536  + 255) / 256, 256>>>(blkW1,  Wh + OFF_W1,  Wl + OFF_W1,  65536);

    // ---- stage A: knn + feature + conv_pos + mean_k -> T1 (128 x P) ----
    knn_conv_kernel<<<B_ * N_, 128>>>(x, cpWf, cpWd, T1h, T1l);

    // fc_pos: H0 (256 x P) = fc_pos_W @ T1
    gemm3p<0><<<dim3(128, 2), 256>>>(Wh + OFF_FCPOS, Wl + OFF_FCPOS, 128,
                                     T1h, T1l, H0h, H0l,
                                     nullptr, nullptr, nullptr, nullptr, nullptr,
                                     nullptr, nullptr, nullptr, nullptr, 128);

    for (int i = 0; i < 4; i++) {
        const __half* Mh = (i == 0) ? Wh + OFF_MRG : Wh + OFF_MRG1 + (size_t)(i - 1) * 49152;
        const __half* Ml = (i == 0) ? Wl + OFF_MRG : Wl + OFF_MRG1 + (size_t)(i - 1) * 49152;
        const __half* W0h  = Wh + OFF_W0  + (size_t)i * 32768;
        const __half* W0l  = Wl + OFF_W0  + (size_t)i * 32768;
        const __half* Wd1h = Wh + OFF_WD1 + (size_t)i * 16384;
        const __half* Wd1l = Wl + OFF_WD1 + (size_t)i * 16384;
        const __half* W1h  = Wh + OFF_W1  + (size_t)i * 16384;
        const __half* W1l  = Wl + OFF_W1  + (size_t)i * 16384;
        const int Kin    = (i == 0) ? 256 : 128;
        const float* bd0 = (i == 0) ? nullptr : bWd0;
        const float* bs  = (i == 0) ? nullptr : bWs;
        const float* Pp  = (i == 0) ? nullptr : P128;

        // merged: rows<256 -> a0 (fused VN-relu, p=H0/pooled) into T0;
        //         rows>=256 -> xs (+bias) into T4
        gemm3p<1><<<dim3(128, 3), 256>>>(Mh, Ml, Kin, H0h, H0l,
                                         T0h, T0l, T4h, T4l,
                                         H0h, H0l, Pp, bd0, bs,
                                         nullptr, nullptr, Kin);

        // net = W0 @ a0 -> T1
        gemm3p<0><<<dim3(128, 1), 256>>>(W0h, W0l, 256, T0h, T0l, T1h, T1l,
                                         nullptr, nullptr, nullptr, nullptr, nullptr,
                                         nullptr, nullptr, nullptr, nullptr, 256);

        // a1 = VNrelu(net, Wd1 @ net) -> T2  (fused, p = T1)
        gemm3p<1><<<dim3(128, 1), 256>>>(Wd1h, Wd1l, 128, T1h, T1l,
                                         T2h, T2l, nullptr, nullptr,
                                         T1h, T1l, nullptr, nullptr, nullptr,
                                         nullptr, nullptr, 128);

        // h = W1 @ a1 + xs -> H0 (first 128 rows)
        gemm3p<2><<<dim3(128, 1), 256>>>(W1h, W1l, 128, T2h, T2l,
                                         H0h, H0l, nullptr, nullptr,
                                         nullptr, nullptr, nullptr, nullptr, nullptr,
                                         T4h, T4l, 128);

        // pooled -> P128
        pool_h<<<H_ * 24, 128>>>(H0h, H0l, P128);

        // fold pooled half of next layer's Wd0/Ws into bias vectors
        if (i < 3) {
            bias_k<<<256, 24>>>(blkWd0 + (size_t)(i + 1) * 256 * 256, 256, P128, bWd0);
            bias_k<<<128, 24>>>(blkWs  + (size_t)(i + 1) * 128 * 256, 256, P128, bWs);
        }
    }

    head_kernel<<<B_, 128>>>(P128, actWd, fccW, out);

    (void)in_sizes; (void)n_in; (void)out_size;
}

// round 13
// speedup vs baseline: 2.6612x; 1.0925x over previous
#include <cuda_runtime.h>
#include <cuda_fp16.h>
#include <math_constants.h>
#include <cstdint>

// ---------------------------------------------------------------------------
// VN_Resnet_Encoder — B=8, N=1024, k=20, H=128, LAYER_NUM=4
// Column layout: col = (b*3 + d)*1024 + n,  P = 24576
// Split-fp16 (hi+lo) storage; mma.m16n8k16 x3 GEMMs (generic PTX only).
// cp.async 3-stage pipeline + ldmatrix fragment loads; fused VN epilogues.
// ---------------------------------------------------------------------------

#define B_      8
#define N_      1024
#define KNN_    20
#define H_      128
#define PCOLS   24576
#define EPS_    1e-6f

// ---------------- scratch (static device globals; no allocation) -----------
__device__ __half g_H0h[256 * PCOLS], g_H0l[256 * PCOLS];
__device__ __half g_T0h[256 * PCOLS], g_T0l[256 * PCOLS];
__device__ __half g_T1h[128 * PCOLS], g_T1l[128 * PCOLS];
__device__ __half g_T2h[128 * PCOLS], g_T2l[128 * PCOLS];
__device__ __half g_T4h[128 * PCOLS], g_T4l[128 * PCOLS];
__device__ float  g_P128[H_ * 24];
__device__ float  g_bWd0[256 * 24];
__device__ float  g_bWs [128 * 24];

// pre-split weight pool (fp16 hi/lo planes)
#define OFF_FCPOS 0                       // 256x128
#define OFF_MRG   32768                   // L0: 384x256
#define OFF_MRG1  131072                  // L1-3: 384x128 each
#define OFF_W0    278528                  // 4 x 128x256
#define OFF_WD1   409600                  // 4 x 128x128
#define OFF_W1    475136                  // 4 x 128x128
#define WPOOL     540672
__device__ __half g_Wh[WPOOL], g_Wl[WPOOL];

// ---------------- helpers ---------------------------------------------------
__device__ __forceinline__ void split1(float v, __half& hi, __half& lo) {
    hi = __float2half_rn(v);
    lo = __float2half_rn(v - __half2float(hi));
}

__device__ __forceinline__ void ld8(const __half* ph, const __half* pl, float* out) {
    uint4 uh = *(const uint4*)ph;
    uint4 ul = *(const uint4*)pl;
    const __half2* hh = (const __half2*)&uh;
    const __half2* ll = (const __half2*)&ul;
    #pragma unroll
    for (int j = 0; j < 4; j++) {
        float2 fh = __half22float2(hh[j]);
        float2 fl = __half22float2(ll[j]);
        out[2 * j]     = fh.x + fl.x;
        out[2 * j + 1] = fh.y + fl.y;
    }
}

__device__ __forceinline__ uint32_t smem_u32(const void* p) {
    uint32_t a;
    asm("{ .reg .u64 t; cvta.to.shared.u64 t, %1; cvt.u32.u64 %0, t; }" : "=r"(a) : "l"(p));
    return a;
}
__device__ __forceinline__ void cpa16(uint32_t dst, const void* src) {
    asm volatile("cp.async.cg.shared.global [%0], [%1], 16;" :: "r"(dst), "l"(src));
}
#define CPA_COMMIT() asm volatile("cp.async.commit_group;" ::: "memory")
#define CPA_WAIT1()  asm volatile("cp.async.wait_group 1;" ::: "memory")

__device__ __forceinline__ void ldsm_x4(uint32_t& r0, uint32_t& r1, uint32_t& r2,
                                        uint32_t& r3, uint32_t addr) {
    asm volatile("ldmatrix.sync.aligned.m8n8.x4.shared.b16 {%0,%1,%2,%3}, [%4];"
                 : "=r"(r0), "=r"(r1), "=r"(r2), "=r"(r3) : "r"(addr));
}
__device__ __forceinline__ void ldsm_x4t(uint32_t& r0, uint32_t& r1, uint32_t& r2,
                                         uint32_t& r3, uint32_t addr) {
    asm volatile("ldmatrix.sync.aligned.m8n8.x4.trans.shared.b16 {%0,%1,%2,%3}, [%4];"
                 : "=r"(r0), "=r"(r1), "=r"(r2), "=r"(r3) : "r"(addr));
}

// ---------------------------------------------------------------------------
// Kernel 0a: split fp32 weights -> fp16 hi/lo pool
// ---------------------------------------------------------------------------
__global__ void convw_kernel(const float* __restrict__ src,
                             __half* __restrict__ dh, __half* __restrict__ dl, int n)
{
    int i = blockIdx.x * 256 + threadIdx.x;
    if (i >= n) return;
    __half hi, lo; split1(src[i], hi, lo);
    dh[i] = hi; dl[i] = lo;
}

// Kernel 0b: merged [Wd0(256 rows); Ws(128 rows)] taking first Kin cols
__global__ void repack_merged(const float* __restrict__ Wd0,
                              const float* __restrict__ Ws, int Kin,
                              __half* __restrict__ dh, __half* __restrict__ dl)
{
    int i = blockIdx.x * 256 + threadIdx.x;
    if (i >= 384 * Kin) return;
    int r = i / Kin, c = i - r * Kin;
    float v = (r < 256) ? Wd0[r * 256 + c] : Ws[(r - 256) * 256 + c];
    __half hi, lo; split1(v, hi, lo);
    dh[i] = hi; dl[i] = lo;
}

// ---------------------------------------------------------------------------
// Kernel 1: KNN + graph feature cross + conv_pos + mean_k  (writes T1 planes)
// ---------------------------------------------------------------------------
__global__ __launch_bounds__(128)
void knn_conv_kernel(const float* __restrict__ x,
                     const float* __restrict__ Wf,
                     const float* __restrict__ Wd,
                     __half* __restrict__ Oh, __half* __restrict__ Ol)
{
    __shared__ float px[N_], py[N_], pz[N_];
    __shared__ float sc[N_];
    __shared__ int   nb[KNN_];
    __shared__ float wmax[4];
    __shared__ int   warg[4];

    const int b = blockIdx.x >> 10;
    const int n = blockIdx.x & 1023;
    const float* xb = x + (size_t)b * N_ * 3;

    for (int i = threadIdx.x; i < N_; i += 128) {
        px[i] = xb[i * 3 + 0];
        py[i] = xb[i * 3 + 1];
        pz[i] = xb[i * 3 + 2];
    }
    __syncthreads();

    const float cx = px[n], cy = py[n], cz = pz[n];

    for (int i = threadIdx.x; i < N_; i += 128) {
        float dx = px[i] - cx, dy = py[i] - cy, dz = pz[i] - cz;
        sc[i] = -(dx * dx + dy * dy + dz * dz);
    }
    __syncthreads();

    const int lane = threadIdx.x & 31, wrp = threadIdx.x >> 5;

    for (int kk = 0; kk < KNN_; kk++) {
        float best = -CUDART_INF_F;
        int   bi   = 1 << 30;
        for (int i = threadIdx.x; i < N_; i += 128) {
            float s = sc[i];
            if (s > best || (s == best && i < bi)) { best = s; bi = i; }
        }
        #pragma unroll
        for (int o = 16; o; o >>= 1) {
            float ob = __shfl_down_sync(0xffffffffu, best, o);
            int   oi = __shfl_down_sync(0xffffffffu, bi,   o);
            if (ob > best || (ob == best && oi < bi)) { best = ob; bi = oi; }
        }
        if (lane == 0) { wmax[wrp] = best; warg[wrp] = bi; }
        __syncthreads();
        if (threadIdx.x == 0) {
            float bb = wmax[0]; int ii = warg[0];
            #pragma unroll
            for (int w = 1; w < 4; w++)
                if (wmax[w] > bb || (wmax[w] == bb && warg[w] < ii)) { bb = wmax[w]; ii = warg[w]; }
            nb[kk] = ii;
            sc[ii] = -CUDART_INF_F;
        }
        __syncthreads();
    }

    const int h = threadIdx.x;
    const float wf0 = Wf[h * 3 + 0], wf1 = Wf[h * 3 + 1], wf2 = Wf[h * 3 + 2];
    const float wd0 = Wd[h * 3 + 0], wd1 = Wd[h * 3 + 1], wd2 = Wd[h * 3 + 2];

    float a0 = 0.f, a1 = 0.f, a2 = 0.f;
    #pragma unroll 4
    for (int kk = 0; kk < KNN_; kk++) {
        int j = nb[kk];
        float nx = px[j], ny = py[j], nz = pz[j];
        float e0 = nx - cx, e1 = ny - cy, e2 = nz - cz;
        float r0 = ny * cz - nz * cy;
        float r1 = nz * cx - nx * cz;
        float r2 = nx * cy - ny * cx;

        float pd0 = wf0 * e0 + wf1 * cx + wf2 * r0;
        float pd1 = wf0 * e1 + wf1 * cy + wf2 * r1;
        float pd2 = wf0 * e2 + wf1 * cz + wf2 * r2;
        float dd0 = wd0 * e0 + wd1 * cx + wd2 * r0;
        float dd1 = wd0 * e1 + wd1 * cy + wd2 * r1;
        float dd2 = wd0 * e2 + wd1 * cz + wd2 * r2;

        float dot = pd0 * dd0 + pd1 * dd1 + pd2 * dd2;
        float dsq = dd0 * dd0 + dd1 * dd1 + dd2 * dd2;
        float f   = dot / (dsq + EPS_);
        bool  pos = (dot >= 0.f);
        a0 += 0.2f * pd0 + 0.8f * (pos ? pd0 : pd0 - f * dd0);
        a1 += 0.2f * pd1 + 0.8f * (pos ? pd1 : pd1 - f * dd1);
        a2 += 0.2f * pd2 + 0.8f * (pos ? pd2 : pd2 - f * dd2);
    }

    size_t base = (size_t)h * PCOLS + (size_t)b * 3 * N_ + n;
    __half hi, lo;
    split1(a0 * (1.0f / KNN_), hi, lo); Oh[base         ] = hi; Ol[base         ] = lo;
    split1(a1 * (1.0f / KNN_), hi, lo); Oh[base + N_    ] = hi; Ol[base + N_    ] = lo;
    split1(a2 * (1.0f / KNN_), hi, lo); Oh[base + 2 * N_] = hi; Ol[base + 2 * N_] = lo;
}

// ---------------------------------------------------------------------------
// Kernel 2: 3-plane batched split-fp16 x3 GEMM with cp.async + ldmatrix.
// Block: 128(m) x 64(n) x 3 spatial planes. BK=32, 3 pipeline stages.
// SMEM stage layout (40960 B):
//   A[pl][m][k] : pl*8192 + m*64 + ((k/8 ^ ((m>>1)&3))*16 + (k&7)*2)
//   B[p][pl][k][n] : 16384 + (p*2+pl)*4096 + k*128 + ((n/8 ^ (k&7))*16 + (n&7)*2)
// MODE 0: plain (+bias1) ; MODE 1: VN-relu / xs split ; MODE 2: +residual
// ---------------------------------------------------------------------------
#define MMA_F16(c0,c1,c2,c3,a0,a1,a2,a3,b0,b1)                               \
    asm volatile("mma.sync.aligned.m16n8k16.row.col.f32.f16.f16.f32 "        \
        "{%0,%1,%2,%3},{%4,%5,%6,%7},{%8,%9},{%0,%1,%2,%3};"                 \
        : "+f"(c0),"+f"(c1),"+f"(c2),"+f"(c3)                                \
        : "r"(a0),"r"(a1),"r"(a2),"r"(a3),"r"(b0),"r"(b1))

#define STAGE_BYTES 40960
#define GSMEM_TOTAL (3 * STAGE_BYTES)

template<int MODE>
__global__ __launch_bounds__(256)
void gemm3p(const __half* __restrict__ Wh_, const __half* __restrict__ Wl_, int lda,
            const __half* __restrict__ Xh, const __half* __restrict__ Xl,
            __half* __restrict__ Ch, __half* __restrict__ Cl,
            __half* __restrict__ C2h, __half* __restrict__ C2l,
            const __half* __restrict__ Ph, const __half* __restrict__ Pl,
            const float* __restrict__ Pp,
            const float* __restrict__ bias1, const float* __restrict__ bias2,
            const __half* __restrict__ A2h, const __half* __restrict__ A2l,
            int K)
{
    extern __shared__ char smem[];
    const uint32_t smem_base = smem_u32(smem);

    const int t     = threadIdx.x;
    const int q     = blockIdx.x;          // 0..127
    const int bb    = q >> 4;
    const int ntile = q & 15;
    const int bcol  = bb * 3072 + ntile * 64;
    const int bd0   = bb * 3;
    const int m0    = blockIdx.y * 128;
    const int warp  = t >> 5, lane = t & 31;
    const int wm    = (warp & 3) * 32;
    const int wn    = (warp >> 2) * 32;
    const int g     = lane >> 2, tg = lane & 3;

    float acc[3][2][4][4];
    #pragma unroll
    for (int p = 0; p < 3; p++)
        #pragma unroll
        for (int i = 0; i < 2; i++)
            #pragma unroll
            for (int j = 0; j < 4; j++)
                #pragma unroll
                for (int l = 0; l < 4; l++) acc[p][i][j][l] = 0.f;

    // ---- stage loader: A (2 planes x 128 x 32) + B (3 x 2 x 32 x 64) ------
    auto load_stage = [&](int st, int k0) {
        const uint32_t base = smem_base + st * STAGE_BYTES;
        #pragma unroll
        for (int i = 0; i < 4; i++) {                  // A: 1024 16B chunks
            int id = t + i * 256;
            int pl = id >> 9;
            int rem = id & 511;
            int m = rem >> 2, c = rem & 3;
            const __half* src = (pl ? Wl_ : Wh_) + (size_t)(m0 + m) * lda + k0 + c * 8;
            uint32_t dst = base + pl * 8192 + m * 64 + ((c ^ ((m >> 1) & 3)) * 16);
            cpa16(dst, src);
        }
        #pragma unroll
        for (int i = 0; i < 6; i++) {                  // B: 1536 16B chunks
            int id = t + i * 256;
            int ppl = id >> 8;                         // p*2+pl, 0..5
            int rem = id & 255;
            int k = rem >> 3, c = rem & 7;
            int p = ppl >> 1, pl = ppl & 1;
            const __half* src = (pl ? Xl : Xh) + (size_t)(k0 + k) * PCOLS + bcol + p * 1024 + c * 8;
            uint32_t dst = base + 16384 + ppl * 4096 + k * 128 + ((c ^ (k & 7)) * 16);
            cpa16(dst, src);
        }
        CPA_COMMIT();
    };

    const int nch = K >> 5;
    load_stage(0, 0);
    load_stage(1, 32);

    for (int ck = 0; ck < nch; ck++) {
        CPA_WAIT1();
        __syncthreads();
        if (ck + 2 < nch) load_stage((ck + 2) % 3, (ck + 2) * 32);

        const uint32_t sb = smem_base + (ck % 3) * STAGE_BYTES;
        #pragma unroll
        for (int ks = 0; ks < 2; ks++) {
            const int kb = ks * 16;
            // A fragments via ldmatrix.x4 (hi and lo planes)
            uint32_t ah[2][4], al[2][4];
            #pragma unroll
            for (int mt = 0; mt < 2; mt++) {
                int row = wm + mt * 16 + (lane & 15);
                int chunk = (kb >> 3) + (lane >> 4);
                uint32_t off = sb + row * 64 + ((chunk ^ ((row >> 1) & 3)) * 16);
                ldsm_x4(ah[mt][0], ah[mt][1], ah[mt][2], ah[mt][3], off);
                ldsm_x4(al[mt][0], al[mt][1], al[mt][2], al[mt][3], off + 8192);
            }
            #pragma unroll
            for (int p = 0; p < 3; p++) {
                // B fragments via ldmatrix.x4.trans (2 n-tile pairs, hi/lo)
                uint32_t bh[2][4], bl[2][4];
                int brow = kb + (lane & 15);
                #pragma unroll
                for (int j = 0; j < 2; j++) {
                    int nc = wn + j * 16 + (lane >> 4) * 8;
                    uint32_t offb = sb + 16384 + (p * 2) * 4096 + brow * 128
                                  + (((nc >> 3) ^ (brow & 7)) * 16);
                    ldsm_x4t(bh[j][0], bh[j][1], bh[j][2], bh[j][3], offb);
                    ldsm_x4t(bl[j][0], bl[j][1], bl[j][2], bl[j][3], offb + 4096);
                }
                #pragma unroll
                for (int nt = 0; nt < 4; nt++) {
                    const int jj = nt >> 1, qq = (nt & 1) * 2;
                    uint32_t bh0 = bh[jj][qq], bh1 = bh[jj][qq + 1];
                    uint32_t bl0 = bl[jj][qq], bl1 = bl[jj][qq + 1];
                    #pragma unroll
                    for (int mt = 0; mt < 2; mt++) {
                        MMA_F16(acc[p][mt][nt][0], acc[p][mt][nt][1], acc[p][mt][nt][2], acc[p][mt][nt][3],
                                al[mt][0], al[mt][1], al[mt][2], al[mt][3], bh0, bh1);
                        MMA_F16(acc[p][mt][nt][0], acc[p][mt][nt][1], acc[p][mt][nt][2], acc[p][mt][nt][3],
                                ah[mt][0], ah[mt][1], ah[mt][2], ah[mt][3], bl0, bl1);
                        MMA_F16(acc[p][mt][nt][0], acc[p][mt][nt][1], acc[p][mt][nt][2], acc[p][mt][nt][3],
                                ah[mt][0], ah[mt][1], ah[mt][2], ah[mt][3], bh0, bh1);
                    }
                }
            }
        }
    }

    // -------------------- epilogue (registers + gmem only) --------------------
    #pragma unroll
    for (int mt = 0; mt < 2; mt++) {
        #pragma unroll
        for (int ri = 0; ri < 2; ri++) {
            const int rabs = m0 + wm + mt * 16 + g + ri * 8;
            #pragma unroll
            for (int nt = 0; nt < 4; nt++) {
                const int col = bcol + wn + nt * 8 + 2 * tg;
                float vx[3], vy[3];
                #pragma unroll
                for (int d = 0; d < 3; d++) {
                    vx[d] = acc[d][mt][nt][2 * ri + 0];
                    vy[d] = acc[d][mt][nt][2 * ri + 1];
                }

                if (MODE == 0) {
                    #pragma unroll
                    for (int d = 0; d < 3; d++) {
                        float bv = bias1 ? bias1[rabs * 24 + bd0 + d] : 0.f;
                        float ox = vx[d] + bv, oy = vy[d] + bv;
                        size_t o = (size_t)rabs * PCOLS + col + d * 1024;
                        __half hx, lx, hy, ly;
                        split1(ox, hx, lx); split1(oy, hy, ly);
                        *(__half2*)(Ch + o) = __halves2half2(hx, hy);
                        *(__half2*)(Cl + o) = __halves2half2(lx, ly);
                    }
                } else if (MODE == 1) {
                    if (rabs < 256) {
                        if (bias1) {
                            #pragma unroll
                            for (int d = 0; d < 3; d++) {
                                float bv = bias1[rabs * 24 + bd0 + d];
                                vx[d] += bv; vy[d] += bv;
                            }
                        }
                        float pxv[3], pyv[3];
                        if (Pp != nullptr && rabs >= 128) {
                            #pragma unroll
                            for (int d = 0; d < 3; d++) {
                                float pv = Pp[(rabs - 128) * 24 + bd0 + d];
                                pxv[d] = pv; pyv[d] = pv;
                            }
                        } else {
                            #pragma unroll
                            for (int d = 0; d < 3; d++) {
                                size_t o = (size_t)rabs * PCOLS + col + d * 1024;
                                float2 fh = __half22float2(*(const __half2*)(Ph + o));
                                float2 fl = __half22float2(*(const __half2*)(Pl + o));
                                pxv[d] = fh.x + fl.x; pyv[d] = fh.y + fl.y;
                            }
                        }
                        float dotx = 0.f, dsqx = 0.f, doty = 0.f, dsqy = 0.f;
                        #pragma unroll
                        for (int d = 0; d < 3; d++) {
                            dotx += pxv[d] * vx[d]; dsqx += vx[d] * vx[d];
                            doty += pyv[d] * vy[d]; dsqy += vy[d] * vy[d];
                        }
                        float fx = dotx / (dsqx + EPS_), fy = doty / (dsqy + EPS_);
                        bool posx = (dotx >= 0.f), posy = (doty >= 0.f);
                        #pragma unroll
                        for (int d = 0; d < 3; d++) {
                            float ox = posx ? pxv[d] : pxv[d] - fx * vx[d];
                            float oy = posy ? pyv[d] : pyv[d] - fy * vy[d];
                            size_t o = (size_t)rabs * PCOLS + col + d * 1024;
                            __half hx, lx, hy, ly;
                            split1(ox, hx, lx); split1(oy, hy, ly);
                            *(__half2*)(Ch + o) = __halves2half2(hx, hy);
                            *(__half2*)(Cl + o) = __halves2half2(lx, ly);
                        }
                    } else {
                        const int rr = rabs - 256;
                        #pragma unroll
                        for (int d = 0; d < 3; d++) {
                            float bv = bias2 ? bias2[rr * 24 + bd0 + d] : 0.f;
                            float ox = vx[d] + bv, oy = vy[d] + bv;
                            size_t o = (size_t)rr * PCOLS + col + d * 1024;
                            __half hx, lx, hy, ly;
                            split1(ox, hx, lx); split1(oy, hy, ly);
                            *(__half2*)(C2h + o) = __halves2half2(hx, hy);
                            *(__half2*)(C2l + o) = __halves2half2(lx, ly);
                        }
                    }
                } else { // MODE == 2 : residual add
                    #pragma unroll
                    for (int d = 0; d < 3; d++) {
                        size_t o = (size_t)rabs * PCOLS + col + d * 1024;
                        float2 fh = __half22float2(*(const __half2*)(A2h + o));
                        float2 fl = __half22float2(*(const __half2*)(A2l + o));
                        float ox = vx[d] + fh.x + fl.x;
                        float oy = vy[d] + fh.y + fl.y;
                        __half hx, lx, hy, ly;
                        split1(ox, hx, lx); split1(oy, hy, ly);
                        *(__half2*)(Ch + o) = __halves2half2(hx, hy);
                        *(__half2*)(Cl + o) = __halves2half2(lx, ly);
                    }
                }
            }
        }
    }
}

// ---------------------------------------------------------------------------
// Kernel 3: pool-only. P128[c][bd] = mean_n H[c, bd*1024 + n]
// ---------------------------------------------------------------------------
__global__ __launch_bounds__(128)
void pool_h(const __half* __restrict__ Hh, const __half* __restrict__ Hl,
            float* __restrict__ P)
{
    __shared__ float red[4];
    int c  = blockIdx.x / 24;
    int bd = blockIdx.x % 24;
    size_t base = (size_t)c * PCOLS + (size_t)bd * 1024 + threadIdx.x * 8;
    float v[8];
    ld8(Hh + base, Hl + base, v);
    float s = 0.f;
    #pragma unroll
    for (int j = 0; j < 8; j++) s += v[j];
    #pragma unroll
    for (int o = 16; o; o >>= 1) s += __shfl_down_sync(0xffffffffu, s, o);
    if ((threadIdx.x & 31) == 0) red[threadIdx.x >> 5] = s;
    __syncthreads();
    if (threadIdx.x == 0)
        P[c * 24 + bd] = (red[0] + red[1] + red[2] + red[3]) * (1.f / N_);
}

// ---------------------------------------------------------------------------
// Kernel 4: bias[m][bd] = sum_c W[m][128+c] * P[c][bd]   (fp32 weights)
// ---------------------------------------------------------------------------
__global__ void bias_k(const float* __restrict__ W, int lda,
                       const float* __restrict__ P, float* __restrict__ out)
{
    int m = blockIdx.x, bd = threadIdx.x;   // 24 threads
    float s = 0.f;
    #pragma unroll 8
    for (int c = 0; c < 128; c++)
        s += W[(size_t)m * lda + 128 + c] * P[c * 24 + bd];
    out[m * 24 + bd] = s;
}

// ---------------------------------------------------------------------------
// Kernel 5: head (fp32, tiny)
// ---------------------------------------------------------------------------
__global__ __launch_bounds__(128)
void head_kernel(const float* __restrict__ P, const float* __restrict__ Wd,
                 const float* __restrict__ Wc, float* __restrict__ out)
{
    __shared__ float hid[H_][3];
    __shared__ float act[H_][3];
    const int b = blockIdx.x, h = threadIdx.x;

    hid[h][0] = P[h * 24 + b * 3 + 0];
    hid[h][1] = P[h * 24 + b * 3 + 1];
    hid[h][2] = P[h * 24 + b * 3 + 2];
    __syncthreads();

    float d0 = 0.f, d1 = 0.f, d2 = 0.f;
    #pragma unroll 8
    for (int c = 0; c < H_; c++) {
        float w = Wd[h * H_ + c];
        d0 = fmaf(w, hid[c][0], d0);
        d1 = fmaf(w, hid[c][1], d1);
        d2 = fmaf(w, hid[c][2], d2);
    }
    float p0 = hid[h][0], p1 = hid[h][1], p2 = hid[h][2];
    float dot = p0 * d0 + p1 * d1 + p2 * d2;
    float dsq = d0 * d0 + d1 * d1 + d2 * d2;
    float f   = dot / (dsq + EPS_);
    bool  pos = (dot >= 0.f);
    act[h][0] = 0.2f * p0 + 0.8f * (pos ? p0 : p0 - f * d0);
    act[h][1] = 0.2f * p1 + 0.8f * (pos ? p1 : p1 - f * d1);
    act[h][2] = 0.2f * p2 + 0.8f * (pos ? p2 : p2 - f * d2);
    __syncthreads();

    float o0 = 0.f, o1 = 0.f, o2 = 0.f;
    #pragma unroll 8
    for (int c = 0; c < H_; c++) {
        float w = Wc[h * H_ + c];
        o0 = fmaf(w, act[c][0], o0);
        o1 = fmaf(w, act[c][1], o1);
        o2 = fmaf(w, act[c][2], o2);
    }
    out[b * (H_ * 3) + h * 3 + 0] = o0;
    out[b * (H_ * 3) + h * 3 + 1] = o1;
    out[b * (H_ * 3) + h * 3 + 2] = o2;
}

// ---------------------------------------------------------------------------
// launcher
// ---------------------------------------------------------------------------
extern "C" void kernel_launch(void* const* d_in, const int* in_sizes, int n_in,
                              void* d_out, int out_size)
{
    const float* x       = (const float*)d_in[0];
    const float* cpWf    = (const float*)d_in[1];
    const float* cpWd    = (const float*)d_in[2];
    const float* fcposW  = (const float*)d_in[3];   // (256,128)
    const float* blkWd0  = (const float*)d_in[4];   // (4,256,256)
    const float* blkW0   = (const float*)d_in[5];   // (4,128,256)
    const float* blkWd1  = (const float*)d_in[6];   // (4,128,128)
    const float* blkW1   = (const float*)d_in[7];   // (4,128,128)
    const float* blkWs   = (const float*)d_in[8];   // (4,128,256)
    const float* actWd   = (const float*)d_in[9];
    const float* fccW    = (const float*)d_in[10];
    float* out = (float*)d_out;

    __half *H0h, *H0l, *T0h, *T0l, *T1h, *T1l, *T2h, *T2l, *T4h, *T4l, *Wh, *Wl;
    float *P128, *bWd0, *bWs;
    cudaGetSymbolAddress((void**)&H0h, g_H0h); cudaGetSymbolAddress((void**)&H0l, g_H0l);
    cudaGetSymbolAddress((void**)&T0h, g_T0h); cudaGetSymbolAddress((void**)&T0l, g_T0l);
    cudaGetSymbolAddress((void**)&T1h, g_T1h); cudaGetSymbolAddress((void**)&T1l, g_T1l);
    cudaGetSymbolAddress((void**)&T2h, g_T2h); cudaGetSymbolAddress((void**)&T2l, g_T2l);
    cudaGetSymbolAddress((void**)&T4h, g_T4h); cudaGetSymbolAddress((void**)&T4l, g_T4l);
    cudaGetSymbolAddress((void**)&Wh,  g_Wh);  cudaGetSymbolAddress((void**)&Wl,  g_Wl);
    cudaGetSymbolAddress((void**)&P128, g_P128);
    cudaGetSymbolAddress((void**)&bWd0, g_bWd0);
    cudaGetSymbolAddress((void**)&bWs,  g_bWs);

    cudaFuncSetAttribute(gemm3p<0>, cudaFuncAttributeMaxDynamicSharedMemorySize, GSMEM_TOTAL);
    cudaFuncSetAttribute(gemm3p<1>, cudaFuncAttributeMaxDynamicSharedMemorySize, GSMEM_TOTAL);
    cudaFuncSetAttribute(gemm3p<2>, cudaFuncAttributeMaxDynamicSharedMemorySize, GSMEM_TOTAL);

    // ---- weight conversion / packing ----
    convw_kernel<<<(32768 + 255) / 256, 256>>>(fcposW, Wh + OFF_FCPOS, Wl + OFF_FCPOS, 32768);
    repack_merged<<<(384 * 256 + 255) / 256, 256>>>(blkWd0, blkWs, 256,
                                                    Wh + OFF_MRG, Wl + OFF_MRG);
    for (int i = 1; i < 4; i++) {
        repack_merged<<<(384 * 128 + 255) / 256, 256>>>(
            blkWd0 + (size_t)i * 256 * 256, blkWs + (size_t)i * 128 * 256, 128,
            Wh + OFF_MRG1 + (size_t)(i - 1) * 49152,
            Wl + OFF_MRG1 + (size_t)(i - 1) * 49152);
    }
    convw_kernel<<<(131072 + 255) / 256, 256>>>(blkW0,  Wh + OFF_W0,  Wl + OFF_W0,  131072);
    convw_kernel<<<(65536  + 255) / 256, 256>>>(blkWd1, Wh + OFF_WD1, Wl + OFF_WD1, 65536);
    convw_kernel<<<(65536  + 255) / 256, 256>>>(blkW1,  Wh + OFF_W1,  Wl + OFF_W1,  65536);

    // ---- stage A: knn + feature + conv_pos + mean_k -> T1 (128 x P) ----
    knn_conv_kernel<<<B_ * N_, 128>>>(x, cpWf, cpWd, T1h, T1l);

    // fc_pos: H0 (256 x P) = fc_pos_W @ T1
    gemm3p<0><<<dim3(128, 2), 256, GSMEM_TOTAL>>>(
        Wh + OFF_FCPOS, Wl + OFF_FCPOS, 128, T1h, T1l, H0h, H0l,
        nullptr, nullptr, nullptr, nullptr, nullptr,
        nullptr, nullptr, nullptr, nullptr, 128);

    for (int i = 0; i < 4; i++) {
        const __half* Mh = (i == 0) ? Wh + OFF_MRG : Wh + OFF_MRG1 + (size_t)(i - 1) * 49152;
        const __half* Ml = (i == 0) ? Wl + OFF_MRG : Wl + OFF_MRG1 + (size_t)(i - 1) * 49152;
        const __half* W0h  = Wh + OFF_W0  + (size_t)i * 32768;
        const __half* W0l  = Wl + OFF_W0  + (size_t)i * 32768;
        const __half* Wd1h = Wh + OFF_WD1 + (size_t)i * 16384;
        const __half* Wd1l = Wl + OFF_WD1 + (size_t)i * 16384;
        const __half* W1h  = Wh + OFF_W1  + (size_t)i * 16384;
        const __half* W1l  = Wl + OFF_W1  + (size_t)i * 16384;
        const int Kin    = (i == 0) ? 256 : 128;
        const float* bd0 = (i == 0) ? nullptr : bWd0;
        const float* bs  = (i == 0) ? nullptr : bWs;
        const float* Pp  = (i == 0) ? nullptr : P128;

        // merged: rows<256 -> a0 (fused VN-relu, p=H0/pooled) into T0;
        //         rows>=256 -> xs (+bias) into T4
        gemm3p<1><<<dim3(128, 3), 256, GSMEM_TOTAL>>>(
            Mh, Ml, Kin, H0h, H0l, T0h, T0l, T4h, T4l,
            H0h, H0l, Pp, bd0, bs, nullptr, nullptr, Kin);

        // net = W0 @ a0 -> T1
        gemm3p<0><<<dim3(128, 1), 256, GSMEM_TOTAL>>>(
            W0h, W0l, 256, T0h, T0l, T1h, T1l,
            nullptr, nullptr, nullptr, nullptr, nullptr,
            nullptr, nullptr, nullptr, nullptr, 256);

        // a1 = VNrelu(net, Wd1 @ net) -> T2  (fused, p = T1)
        gemm3p<1><<<dim3(128, 1), 256, GSMEM_TOTAL>>>(
            Wd1h, Wd1l, 128, T1h, T1l, T2h, T2l, nullptr, nullptr,
            T1h, T1l, nullptr, nullptr, nullptr, nullptr, nullptr, 128);

        // h = W1 @ a1 + xs -> H0 (first 128 rows)
        gemm3p<2><<<dim3(128, 1), 256, GSMEM_TOTAL>>>(
            W1h, W1l, 128, T2h, T2l, H0h, H0l, nullptr, nullptr,
            nullptr, nullptr, nullptr, nullptr, nullptr, T4h, T4l, 128);

        // pooled -> P128
        pool_h<<<H_ * 24, 128>>>(H0h, H0l, P128);

        // fold pooled half of next layer's Wd0/Ws into bias vectors
        if (i < 3) {
            bias_k<<<256, 24>>>(blkWd0 + (size_t)(i + 1) * 256 * 256, 256, P128, bWd0);
            bias_k<<<128, 24>>>(blkWs  + (size_t)(i + 1) * 128 * 256, 256, P128, bWs);
        }
    }

    head_kernel<<<B_, 128>>>(P128, actWd, fccW, out);

    (void)in_sizes; (void)n_in; (void)out_size;
}

// round 17
// speedup vs baseline: 2.8605x; 1.0749x over previous
#include <cuda_runtime.h>
#include <cuda_fp16.h>
#include <math_constants.h>
#include <cstdint>

// ---------------------------------------------------------------------------
// VN_Resnet_Encoder — B=8, N=1024, k=20, H=128, LAYER_NUM=4
// Column layout: col = (b*3 + d)*1024 + n,  P = 24576
// Split-fp16 (hi+lo) storage; mma.m16n8k16 x3 GEMMs (generic PTX only).
// cp.async 3-stage pipeline + ldmatrix; fused VN epilogues; fused pooling.
// ---------------------------------------------------------------------------

#define B_      8
#define N_      1024
#define KNN_    20
#define H_      128
#define PCOLS   24576
#define EPS_    1e-6f

// ---------------- scratch (static device globals; no allocation) -----------
__device__ __half g_H0h[256 * PCOLS], g_H0l[256 * PCOLS];
__device__ __half g_T0h[256 * PCOLS], g_T0l[256 * PCOLS];
__device__ __half g_T1h[128 * PCOLS], g_T1l[128 * PCOLS];
__device__ __half g_T2h[128 * PCOLS], g_T2l[128 * PCOLS];
__device__ __half g_T4h[128 * PCOLS], g_T4l[128 * PCOLS];
__device__ float  g_P128[H_ * 24];
__device__ float  g_bWd0[256 * 24];
__device__ float  g_bWs [128 * 24];

// pre-split weight pool (fp16 hi/lo planes)
#define OFF_FCPOS 0                       // 256x128
#define OFF_MRG   32768                   // L0: 384x256
#define OFF_MRG1  131072                  // L1-3: 384x128 each
#define OFF_W0    278528                  // 4 x 128x256
#define OFF_WD1   409600                  // 4 x 128x128
#define OFF_W1    475136                  // 4 x 128x128
#define WPOOL     540672
__device__ __half g_Wh[WPOOL], g_Wl[WPOOL];

// ---------------- helpers ---------------------------------------------------
__device__ __forceinline__ void split1(float v, __half& hi, __half& lo) {
    hi = __float2half_rn(v);
    lo = __float2half_rn(v - __half2float(hi));
}

__device__ __forceinline__ uint32_t smem_u32(const void* p) {
    uint32_t a;
    asm("{ .reg .u64 t; cvta.to.shared.u64 t, %1; cvt.u32.u64 %0, t; }" : "=r"(a) : "l"(p));
    return a;
}
__device__ __forceinline__ void cpa16(uint32_t dst, const void* src) {
    asm volatile("cp.async.cg.shared.global [%0], [%1], 16;" :: "r"(dst), "l"(src));
}
#define CPA_COMMIT() asm volatile("cp.async.commit_group;" ::: "memory")
#define CPA_WAIT1()  asm volatile("cp.async.wait_group 1;" ::: "memory")

__device__ __forceinline__ void ldsm_x4(uint32_t& r0, uint32_t& r1, uint32_t& r2,
                                        uint32_t& r3, uint32_t addr) {
    asm volatile("ldmatrix.sync.aligned.m8n8.x4.shared.b16 {%0,%1,%2,%3}, [%4];"
                 : "=r"(r0), "=r"(r1), "=r"(r2), "=r"(r3) : "r"(addr));
}
__device__ __forceinline__ void ldsm_x4t(uint32_t& r0, uint32_t& r1, uint32_t& r2,
                                         uint32_t& r3, uint32_t addr) {
    asm volatile("ldmatrix.sync.aligned.m8n8.x4.trans.shared.b16 {%0,%1,%2,%3}, [%4];"
                 : "=r"(r0), "=r"(r1), "=r"(r2), "=r"(r3) : "r"(addr));
}

// ---------------------------------------------------------------------------
// Kernel 0: ONE pass for all weight conversion/packing.
// ---------------------------------------------------------------------------
__global__ __launch_bounds__(256)
void prep_all(const float* __restrict__ fcposW,
              const float* __restrict__ blkWd0, const float* __restrict__ blkWs,
              const float* __restrict__ blkW0,  const float* __restrict__ blkWd1,
              const float* __restrict__ blkW1,
              __half* __restrict__ dh, __half* __restrict__ dl)
{
    int i = blockIdx.x * 256 + threadIdx.x;
    if (i >= WPOOL) return;
    float v;
    if (i < OFF_MRG) {
        v = fcposW[i];
    } else if (i < OFF_MRG1) {                 // merged L0, Kin=256
        int j = i - OFF_MRG;
        int r = j >> 8, c = j & 255;
        v = (r < 256) ? blkWd0[r * 256 + c] : blkWs[(r - 256) * 256 + c];
    } else if (i < OFF_W0) {                   // merged L1-3, Kin=128
        int j = i - OFF_MRG1;
        int l = j / 49152 + 1, jj = j % 49152;
        int r = jj >> 7, c = jj & 127;
        v = (r < 256) ? blkWd0[(size_t)l * 65536 + r * 256 + c]
                      : blkWs[(size_t)l * 32768 + (r - 256) * 256 + c];
    } else if (i < OFF_WD1) {
        v = blkW0[i - OFF_W0];
    } else if (i < OFF_W1) {
        v = blkWd1[i - OFF_WD1];
    } else {
        v = blkW1[i - OFF_W1];
    }
    __half hi, lo; split1(v, hi, lo);
    dh[i] = hi; dl[i] = lo;
}

// ---------------------------------------------------------------------------
// Kernel 1: KNN + graph feature cross + conv_pos + mean_k  (writes T1 planes)
// ---------------------------------------------------------------------------
__global__ __launch_bounds__(128)
void knn_conv_kernel(const float* __restrict__ x,
                     const float* __restrict__ Wf,
                     const float* __restrict__ Wd,
                     __half* __restrict__ Oh, __half* __restrict__ Ol)
{
    __shared__ float px[N_], py[N_], pz[N_];
    __shared__ float sc[N_];
    __shared__ int   nb[KNN_];
    __shared__ float wmax[4];
    __shared__ int   warg[4];

    const int b = blockIdx.x >> 10;
    const int n = blockIdx.x & 1023;
    const float* xb = x + (size_t)b * N_ * 3;

    for (int i = threadIdx.x; i < N_; i += 128) {
        px[i] = xb[i * 3 + 0];
        py[i] = xb[i * 3 + 1];
        pz[i] = xb[i * 3 + 2];
    }
    __syncthreads();

    const float cx = px[n], cy = py[n], cz = pz[n];

    for (int i = threadIdx.x; i < N_; i += 128) {
        float dx = px[i] - cx, dy = py[i] - cy, dz = pz[i] - cz;
        sc[i] = -(dx * dx + dy * dy + dz * dz);
    }
    __syncthreads();

    const int lane = threadIdx.x & 31, wrp = threadIdx.x >> 5;

    for (int kk = 0; kk < KNN_; kk++) {
        float best = -CUDART_INF_F;
        int   bi   = 1 << 30;
        for (int i = threadIdx.x; i < N_; i += 128) {
            float s = sc[i];
            if (s > best || (s == best && i < bi)) { best = s; bi = i; }
        }
        #pragma unroll
        for (int o = 16; o; o >>= 1) {
            float ob = __shfl_down_sync(0xffffffffu, best, o);
            int   oi = __shfl_down_sync(0xffffffffu, bi,   o);
            if (ob > best || (ob == best && oi < bi)) { best = ob; bi = oi; }
        }
        if (lane == 0) { wmax[wrp] = best; warg[wrp] = bi; }
        __syncthreads();
        if (threadIdx.x == 0) {
            float bb = wmax[0]; int ii = warg[0];
            #pragma unroll
            for (int w = 1; w < 4; w++)
                if (wmax[w] > bb || (wmax[w] == bb && warg[w] < ii)) { bb = wmax[w]; ii = warg[w]; }
            nb[kk] = ii;
            sc[ii] = -CUDART_INF_F;
        }
        __syncthreads();
    }

    const int h = threadIdx.x;
    const float wf0 = Wf[h * 3 + 0], wf1 = Wf[h * 3 + 1], wf2 = Wf[h * 3 + 2];
    const float wd0 = Wd[h * 3 + 0], wd1 = Wd[h * 3 + 1], wd2 = Wd[h * 3 + 2];

    float a0 = 0.f, a1 = 0.f, a2 = 0.f;
    #pragma unroll 4
    for (int kk = 0; kk < KNN_; kk++) {
        int j = nb[kk];
        float nx = px[j], ny = py[j], nz = pz[j];
        float e0 = nx - cx, e1 = ny - cy, e2 = nz - cz;
        float r0 = ny * cz - nz * cy;
        float r1 = nz * cx - nx * cz;
        float r2 = nx * cy - ny * cx;

        float pd0 = wf0 * e0 + wf1 * cx + wf2 * r0;
        float pd1 = wf0 * e1 + wf1 * cy + wf2 * r1;
        float pd2 = wf0 * e2 + wf1 * cz + wf2 * r2;
        float dd0 = wd0 * e0 + wd1 * cx + wd2 * r0;
        float dd1 = wd0 * e1 + wd1 * cy + wd2 * r1;
        float dd2 = wd0 * e2 + wd1 * cz + wd2 * r2;

        float dot = pd0 * dd0 + pd1 * dd1 + pd2 * dd2;
        float dsq = dd0 * dd0 + dd1 * dd1 + dd2 * dd2;
        float f   = dot / (dsq + EPS_);
        bool  pos = (dot >= 0.f);
        a0 += 0.2f * pd0 + 0.8f * (pos ? pd0 : pd0 - f * dd0);
        a1 += 0.2f * pd1 + 0.8f * (pos ? pd1 : pd1 - f * dd1);
        a2 += 0.2f * pd2 + 0.8f * (pos ? pd2 : pd2 - f * dd2);
    }

    size_t base = (size_t)h * PCOLS + (size_t)b * 3 * N_ + n;
    __half hi, lo;
    split1(a0 * (1.0f / KNN_), hi, lo); Oh[base         ] = hi; Ol[base         ] = lo;
    split1(a1 * (1.0f / KNN_), hi, lo); Oh[base + N_    ] = hi; Ol[base + N_    ] = lo;
    split1(a2 * (1.0f / KNN_), hi, lo); Oh[base + 2 * N_] = hi; Ol[base + 2 * N_] = lo;
}

// ---------------------------------------------------------------------------
// Kernel 2: 3-plane batched split-fp16 x3 GEMM, cp.async + ldmatrix.
// MODE 0: plain (+bias1) ; MODE 1: VN-relu / xs split (+optional P zeroing) ;
// MODE 2: +residual, fused pooling into Pacc (and optional h store skip).
// ---------------------------------------------------------------------------
#define MMA_F16(c0,c1,c2,c3,a0,a1,a2,a3,b0,b1)                               \
    asm volatile("mma.sync.aligned.m16n8k16.row.col.f32.f16.f16.f32 "        \
        "{%0,%1,%2,%3},{%4,%5,%6,%7},{%8,%9},{%0,%1,%2,%3};"                 \
        : "+f"(c0),"+f"(c1),"+f"(c2),"+f"(c3)                                \
        : "r"(a0),"r"(a1),"r"(a2),"r"(a3),"r"(b0),"r"(b1))

#define STAGE_BYTES 40960
#define GSMEM_TOTAL (3 * STAGE_BYTES)

template<int MODE>
__global__ __launch_bounds__(256)
void gemm3p(const __half* __restrict__ Wh_, const __half* __restrict__ Wl_, int lda,
            const __half* __restrict__ Xh, const __half* __restrict__ Xl,
            __half* __restrict__ Ch, __half* __restrict__ Cl,
            __half* __restrict__ C2h, __half* __restrict__ C2l,
            const __half* __restrict__ Ph, const __half* __restrict__ Pl,
            const float* __restrict__ Pp,
            const float* __restrict__ bias1, const float* __restrict__ bias2,
            const __half* __restrict__ A2h, const __half* __restrict__ A2l,
            int K, float* __restrict__ Pz, float* __restrict__ Pacc)
{
    extern __shared__ char smem[];
    __shared__ float psm[128][3];
    const uint32_t smem_base = smem_u32(smem);

    const int t     = threadIdx.x;
    const int q     = blockIdx.x;          // 0..127
    const int bb    = q >> 4;
    const int ntile = q & 15;
    const int bcol  = bb * 3072 + ntile * 64;
    const int bd0   = bb * 3;
    const int m0    = blockIdx.y * 128;
    const int warp  = t >> 5, lane = t & 31;
    const int wm    = (warp & 3) * 32;
    const int wn    = (warp >> 2) * 32;
    const int g     = lane >> 2, tg = lane & 3;

    // stream-order-safe P128 zeroing (runs in the launch preceding MODE 2)
    if (MODE == 1 && Pz != nullptr && blockIdx.x == 0 && blockIdx.y == 0) {
        for (int idx = t; idx < 3072; idx += 256) Pz[idx] = 0.f;
    }
    if (MODE == 2) {
        for (int idx = t; idx < 384; idx += 256) psm[idx / 3][idx % 3] = 0.f;
    }

    float acc[3][2][4][4];
    #pragma unroll
    for (int p = 0; p < 3; p++)
        #pragma unroll
        for (int i = 0; i < 2; i++)
            #pragma unroll
            for (int j = 0; j < 4; j++)
                #pragma unroll
                for (int l = 0; l < 4; l++) acc[p][i][j][l] = 0.f;

    auto load_stage = [&](int st, int k0) {
        const uint32_t base = smem_base + st * STAGE_BYTES;
        #pragma unroll
        for (int i = 0; i < 4; i++) {                  // A: 1024 16B chunks
            int id = t + i * 256;
            int pl = id >> 9;
            int rem = id & 511;
            int m = rem >> 2, c = rem & 3;
            const __half* src = (pl ? Wl_ : Wh_) + (size_t)(m0 + m) * lda + k0 + c * 8;
            uint32_t dst = base + pl * 8192 + m * 64 + ((c ^ ((m >> 1) & 3)) * 16);
            cpa16(dst, src);
        }
        #pragma unroll
        for (int i = 0; i < 6; i++) {                  // B: 1536 16B chunks
            int id = t + i * 256;
            int ppl = id >> 8;                         // p*2+pl, 0..5
            int rem = id & 255;
            int k = rem >> 3, c = rem & 7;
            int p = ppl >> 1, pl = ppl & 1;
            const __half* src = (pl ? Xl : Xh) + (size_t)(k0 + k) * PCOLS + bcol + p * 1024 + c * 8;
            uint32_t dst = base + 16384 + ppl * 4096 + k * 128 + ((c ^ (k & 7)) * 16);
            cpa16(dst, src);
        }
        CPA_COMMIT();
    };

    const int nch = K >> 5;
    load_stage(0, 0);
    load_stage(1, 32);

    for (int ck = 0; ck < nch; ck++) {
        CPA_WAIT1();
        __syncthreads();
        if (ck + 2 < nch) load_stage((ck + 2) % 3, (ck + 2) * 32);

        const uint32_t sb = smem_base + (ck % 3) * STAGE_BYTES;
        #pragma unroll
        for (int ks = 0; ks < 2; ks++) {
            const int kb = ks * 16;
            uint32_t ah[2][4], al[2][4];
            #pragma unroll
            for (int mt = 0; mt < 2; mt++) {
                int row = wm + mt * 16 + (lane & 15);
                int chunk = (kb >> 3) + (lane >> 4);
                uint32_t off = sb + row * 64 + ((chunk ^ ((row >> 1) & 3)) * 16);
                ldsm_x4(ah[mt][0], ah[mt][1], ah[mt][2], ah[mt][3], off);
                ldsm_x4(al[mt][0], al[mt][1], al[mt][2], al[mt][3], off + 8192);
            }
            #pragma unroll
            for (int p = 0; p < 3; p++) {
                uint32_t bh[2][4], bl[2][4];
                int brow = kb + (lane & 15);
                #pragma unroll
                for (int j = 0; j < 2; j++) {
                    int nc = wn + j * 16 + (lane >> 4) * 8;
                    uint32_t offb = sb + 16384 + (p * 2) * 4096 + brow * 128
                                  + (((nc >> 3) ^ (brow & 7)) * 16);
                    ldsm_x4t(bh[j][0], bh[j][1], bh[j][2], bh[j][3], offb);
                    ldsm_x4t(bl[j][0], bl[j][1], bl[j][2], bl[j][3], offb + 4096);
                }
                #pragma unroll
                for (int nt = 0; nt < 4; nt++) {
                    const int jj = nt >> 1, qq = (nt & 1) * 2;
                    uint32_t bh0 = bh[jj][qq], bh1 = bh[jj][qq + 1];
                    uint32_t bl0 = bl[jj][qq], bl1 = bl[jj][qq + 1];
                    #pragma unroll
                    for (int mt = 0; mt < 2; mt++) {
                        MMA_F16(acc[p][mt][nt][0], acc[p][mt][nt][1], acc[p][mt][nt][2], acc[p][mt][nt][3],
                                al[mt][0], al[mt][1], al[mt][2], al[mt][3], bh0, bh1);
                        MMA_F16(acc[p][mt][nt][0], acc[p][mt][nt][1], acc[p][mt][nt][2], acc[p][mt][nt][3],
                                ah[mt][0], ah[mt][1], ah[mt][2], ah[mt][3], bl0, bl1);
                        MMA_F16(acc[p][mt][nt][0], acc[p][mt][nt][1], acc[p][mt][nt][2], acc[p][mt][nt][3],
                                ah[mt][0], ah[mt][1], ah[mt][2], ah[mt][3], bh0, bh1);
                    }
                }
            }
        }
    }

    // -------------------- epilogue --------------------
    float psum[2][2][3];
    if (MODE == 2) {
        #pragma unroll
        for (int a = 0; a < 2; a++)
            #pragma unroll
            for (int b = 0; b < 2; b++)
                #pragma unroll
                for (int d = 0; d < 3; d++) psum[a][b][d] = 0.f;
    }

    #pragma unroll
    for (int mt = 0; mt < 2; mt++) {
        #pragma unroll
        for (int ri = 0; ri < 2; ri++) {
            const int rabs = m0 + wm + mt * 16 + g + ri * 8;
            #pragma unroll
            for (int nt = 0; nt < 4; nt++) {
                const int col = bcol + wn + nt * 8 + 2 * tg;
                float vx[3], vy[3];
                #pragma unroll
                for (int d = 0; d < 3; d++) {
                    vx[d] = acc[d][mt][nt][2 * ri + 0];
                    vy[d] = acc[d][mt][nt][2 * ri + 1];
                }

                if (MODE == 0) {
                    #pragma unroll
                    for (int d = 0; d < 3; d++) {
                        float bv = bias1 ? bias1[rabs * 24 + bd0 + d] : 0.f;
                        float ox = vx[d] + bv, oy = vy[d] + bv;
                        size_t o = (size_t)rabs * PCOLS + col + d * 1024;
                        __half hx, lx, hy, ly;
                        split1(ox, hx, lx); split1(oy, hy, ly);
                        *(__half2*)(Ch + o) = __halves2half2(hx, hy);
                        *(__half2*)(Cl + o) = __halves2half2(lx, ly);
                    }
                } else if (MODE == 1) {
                    if (rabs < 256) {
                        if (bias1) {
                            #pragma unroll
                            for (int d = 0; d < 3; d++) {
                                float bv = bias1[rabs * 24 + bd0 + d];
                                vx[d] += bv; vy[d] += bv;
                            }
                        }
                        float pxv[3], pyv[3];
                        if (Pp != nullptr && rabs >= 128) {
                            #pragma unroll
                            for (int d = 0; d < 3; d++) {
                                float pv = Pp[(rabs - 128) * 24 + bd0 + d];
                                pxv[d] = pv; pyv[d] = pv;
                            }
                        } else {
                            #pragma unroll
                            for (int d = 0; d < 3; d++) {
                                size_t o = (size_t)rabs * PCOLS + col + d * 1024;
                                float2 fh = __half22float2(*(const __half2*)(Ph + o));
                                float2 fl = __half22float2(*(const __half2*)(Pl + o));
                                pxv[d] = fh.x + fl.x; pyv[d] = fh.y + fl.y;
                            }
                        }
                        float dotx = 0.f, dsqx = 0.f, doty = 0.f, dsqy = 0.f;
                        #pragma unroll
                        for (int d = 0; d < 3; d++) {
                            dotx += pxv[d] * vx[d]; dsqx += vx[d] * vx[d];
                            doty += pyv[d] * vy[d]; dsqy += vy[d] * vy[d];
                        }
                        float fx = dotx / (dsqx + EPS_), fy = doty / (dsqy + EPS_);
                        bool posx = (dotx >= 0.f), posy = (doty >= 0.f);
                        #pragma unroll
                        for (int d = 0; d < 3; d++) {
                            float ox = posx ? pxv[d] : pxv[d] - fx * vx[d];
                            float oy = posy ? pyv[d] : pyv[d] - fy * vy[d];
                            size_t o = (size_t)rabs * PCOLS + col + d * 1024;
                            __half hx, lx, hy, ly;
                            split1(ox, hx, lx); split1(oy, hy, ly);
                            *(__half2*)(Ch + o) = __halves2half2(hx, hy);
                            *(__half2*)(Cl + o) = __halves2half2(lx, ly);
                        }
                    } else {
                        const int rr = rabs - 256;
                        #pragma unroll
                        for (int d = 0; d < 3; d++) {
                            float bv = bias2 ? bias2[rr * 24 + bd0 + d] : 0.f;
                            float ox = vx[d] + bv, oy = vy[d] + bv;
                            size_t o = (size_t)rr * PCOLS + col + d * 1024;
                            __half hx, lx, hy, ly;
                            split1(ox, hx, lx); split1(oy, hy, ly);
                            *(__half2*)(C2h + o) = __halves2half2(hx, hy);
                            *(__half2*)(C2l + o) = __halves2half2(lx, ly);
                        }
                    }
                } else { // MODE == 2 : residual add + fused pooling
                    #pragma unroll
                    for (int d = 0; d < 3; d++) {
                        size_t o = (size_t)rabs * PCOLS + col + d * 1024;
                        float2 fh = __half22float2(*(const __half2*)(A2h + o));
                        float2 fl = __half22float2(*(const __half2*)(A2l + o));
                        float ox = vx[d] + fh.x + fl.x;
                        float oy = vy[d] + fh.y + fl.y;
                        psum[mt][ri][d] += ox + oy;
                        if (Ch) {
                            __half hx, lx, hy, ly;
                            split1(ox, hx, lx); split1(oy, hy, ly);
                            *(__half2*)(Ch + o) = __halves2half2(hx, hy);
                            *(__half2*)(Cl + o) = __halves2half2(lx, ly);
                        }
                    }
                }
            }
        }
    }

    if (MODE == 2) {
        __syncthreads();   // psm zeros visible
        #pragma unroll
        for (int mt = 0; mt < 2; mt++)
            #pragma unroll
            for (int ri = 0; ri < 2; ri++)
                #pragma unroll
                for (int d = 0; d < 3; d++) {
                    float v = psum[mt][ri][d];
                    v += __shfl_xor_sync(0xffffffffu, v, 1);
                    v += __shfl_xor_sync(0xffffffffu, v, 2);
                    if (tg == 0)
                        atomicAdd(&psm[wm + mt * 16 + g + ri * 8][d], v);
                }
        __syncthreads();
        // FIX (R14 bug): stride loop — block has 256 threads but 384 entries
        for (int idx = t; idx < 384; idx += 256) {
            int r = idx / 3, d = idx - 3 * r;
            atomicAdd(Pacc + r * 24 + bd0 + d, psm[r][d] * (1.f / 1024.f));
        }
    }
}

// ---------------------------------------------------------------------------
// Kernel 3: merged bias. m<256: Wd0-half -> bWd0 ; else Ws-half -> bWs
// ---------------------------------------------------------------------------
__global__ void bias2_k(const float* __restrict__ Wd0, const float* __restrict__ Ws,
                        const float* __restrict__ P,
                        float* __restrict__ bWd0, float* __restrict__ bWs)
{
    int m = blockIdx.x, bd = threadIdx.x;   // 24 threads
    const float* W;
    float* o;
    if (m < 256) { W = Wd0 + (size_t)m * 256; o = bWd0 + m * 24; }
    else         { W = Ws + (size_t)(m - 256) * 256; o = bWs + (m - 256) * 24; }
    float s = 0.f;
    #pragma unroll 8
    for (int c = 0; c < 128; c++)
        s += W[128 + c] * P[c * 24 + bd];
    o[bd] = s;
}

// ---------------------------------------------------------------------------
// Kernel 4: head (fp32, tiny)
// ---------------------------------------------------------------------------
__global__ __launch_bounds__(128)
void head_kernel(const float* __restrict__ P, const float* __restrict__ Wd,
                 const float* __restrict__ Wc, float* __restrict__ out)
{
    __shared__ float hid[H_][3];
    __shared__ float act[H_][3];
    const int b = blockIdx.x, h = threadIdx.x;

    hid[h][0] = P[h * 24 + b * 3 + 0];
    hid[h][1] = P[h * 24 + b * 3 + 1];
    hid[h][2] = P[h * 24 + b * 3 + 2];
    __syncthreads();

    float d0 = 0.f, d1 = 0.f, d2 = 0.f;
    #pragma unroll 8
    for (int c = 0; c < H_; c++) {
        float w = Wd[h * H_ + c];
        d0 = fmaf(w, hid[c][0], d0);
        d1 = fmaf(w, hid[c][1], d1);
        d2 = fmaf(w, hid[c][2], d2);
    }
    float p0 = hid[h][0], p1 = hid[h][1], p2 = hid[h][2];
    float dot = p0 * d0 + p1 * d1 + p2 * d2;
    float dsq = d0 * d0 + d1 * d1 + d2 * d2;
    float f   = dot / (dsq + EPS_);
    bool  pos = (dot >= 0.f);
    act[h][0] = 0.2f * p0 + 0.8f * (pos ? p0 : p0 - f * d0);
    act[h][1] = 0.2f * p1 + 0.8f * (pos ? p1 : p1 - f * d1);
    act[h][2] = 0.2f * p2 + 0.8f * (pos ? p2 : p2 - f * d2);
    __syncthreads();

    float o0 = 0.f, o1 = 0.f, o2 = 0.f;
    #pragma unroll 8
    for (int c = 0; c < H_; c++) {
        float w = Wc[h * H_ + c];
        o0 = fmaf(w, act[c][0], o0);
        o1 = fmaf(w, act[c][1], o1);
        o2 = fmaf(w, act[c][2], o2);
    }
    out[b * (H_ * 3) + h * 3 + 0] = o0;
    out[b * (H_ * 3) + h * 3 + 1] = o1;
    out[b * (H_ * 3) + h * 3 + 2] = o2;
}

// ---------------------------------------------------------------------------
// launcher
// ---------------------------------------------------------------------------
extern "C" void kernel_launch(void* const* d_in, const int* in_sizes, int n_in,
                              void* d_out, int out_size)
{
    const float* x       = (const float*)d_in[0];
    const float* cpWf    = (const float*)d_in[1];
    const float* cpWd    = (const float*)d_in[2];
    const float* fcposW  = (const float*)d_in[3];   // (256,128)
    const float* blkWd0  = (const float*)d_in[4];   // (4,256,256)
    const float* blkW0   = (const float*)d_in[5];   // (4,128,256)
    const float* blkWd1  = (const float*)d_in[6];   // (4,128,128)
    const float* blkW1   = (const float*)d_in[7];   // (4,128,128)
    const float* blkWs   = (const float*)d_in[8];   // (4,128,256)
    const float* actWd   = (const float*)d_in[9];
    const float* fccW    = (const float*)d_in[10];
    float* out = (float*)d_out;

    __half *H0h, *H0l, *T0h, *T0l, *T1h, *T1l, *T2h, *T2l, *T4h, *T4l, *Wh, *Wl;
    float *P128, *bWd0, *bWs;
    cudaGetSymbolAddress((void**)&H0h, g_H0h); cudaGetSymbolAddress((void**)&H0l, g_H0l);
    cudaGetSymbolAddress((void**)&T0h, g_T0h); cudaGetSymbolAddress((void**)&T0l, g_T0l);
    cudaGetSymbolAddress((void**)&T1h, g_T1h); cudaGetSymbolAddress((void**)&T1l, g_T1l);
    cudaGetSymbolAddress((void**)&T2h, g_T2h); cudaGetSymbolAddress((void**)&T2l, g_T2l);
    cudaGetSymbolAddress((void**)&T4h, g_T4h); cudaGetSymbolAddress((void**)&T4l, g_T4l);
    cudaGetSymbolAddress((void**)&Wh,  g_Wh);  cudaGetSymbolAddress((void**)&Wl,  g_Wl);
    cudaGetSymbolAddress((void**)&P128, g_P128);
    cudaGetSymbolAddress((void**)&bWd0, g_bWd0);
    cudaGetSymbolAddress((void**)&bWs,  g_bWs);

    cudaFuncSetAttribute(gemm3p<0>, cudaFuncAttributeMaxDynamicSharedMemorySize, GSMEM_TOTAL);
    cudaFuncSetAttribute(gemm3p<1>, cudaFuncAttributeMaxDynamicSharedMemorySize, GSMEM_TOTAL);
    cudaFuncSetAttribute(gemm3p<2>, cudaFuncAttributeMaxDynamicSharedMemorySize, GSMEM_TOTAL);

    // ---- all weight conversion / packing in one launch ----
    prep_all<<<(WPOOL + 255) / 256, 256>>>(fcposW, blkWd0, blkWs, blkW0, blkWd1, blkW1,
                                           Wh, Wl);

    // ---- stage A: knn + feature + conv_pos + mean_k -> T1 (128 x P) ----
    knn_conv_kernel<<<B_ * N_, 128>>>(x, cpWf, cpWd, T1h, T1l);

    // fc_pos: H0 (256 x P) = fc_pos_W @ T1
    gemm3p<0><<<dim3(128, 2), 256, GSMEM_TOTAL>>>(
        Wh + OFF_FCPOS, Wl + OFF_FCPOS, 128, T1h, T1l, H0h, H0l,
        nullptr, nullptr, nullptr, nullptr, nullptr,
        nullptr, nullptr, nullptr, nullptr, 128, nullptr, nullptr);

    for (int i = 0; i < 4; i++) {
        const __half* Mh = (i == 0) ? Wh + OFF_MRG : Wh + OFF_MRG1 + (size_t)(i - 1) * 49152;
        const __half* Ml = (i == 0) ? Wl + OFF_MRG : Wl + OFF_MRG1 + (size_t)(i - 1) * 49152;
        const __half* W0h  = Wh + OFF_W0  + (size_t)i * 32768;
        const __half* W0l  = Wl + OFF_W0  + (size_t)i * 32768;
        const __half* Wd1h = Wh + OFF_WD1 + (size_t)i * 16384;
        const __half* Wd1l = Wl + OFF_WD1 + (size_t)i * 16384;
        const __half* W1h  = Wh + OFF_W1  + (size_t)i * 16384;
        const __half* W1l  = Wl + OFF_W1  + (size_t)i * 16384;
        const int Kin    = (i == 0) ? 256 : 128;
        const float* bd0 = (i == 0) ? nullptr : bWd0;
        const float* bs  = (i == 0) ? nullptr : bWs;
        const float* Pp  = (i == 0) ? nullptr : P128;

        // merged: rows<256 -> a0 (fused VN-relu, p=H0/pooled) into T0;
        //         rows>=256 -> xs (+bias) into T4
        gemm3p<1><<<dim3(128, 3), 256, GSMEM_TOTAL>>>(
            Mh, Ml, Kin, H0h, H0l, T0h, T0l, T4h, T4l,
            H0h, H0l, Pp, bd0, bs, nullptr, nullptr, Kin, nullptr, nullptr);

        // net = W0 @ a0 -> T1
        gemm3p<0><<<dim3(128, 1), 256, GSMEM_TOTAL>>>(
            W0h, W0l, 256, T0h, T0l, T1h, T1l,
            nullptr, nullptr, nullptr, nullptr, nullptr,
            nullptr, nullptr, nullptr, nullptr, 256, nullptr, nullptr);

        // a1 = VNrelu(net, Wd1 @ net) -> T2 ; block(0,0) zeroes P128
        gemm3p<1><<<dim3(128, 1), 256, GSMEM_TOTAL>>>(
            Wd1h, Wd1l, 128, T1h, T1l, T2h, T2l, nullptr, nullptr,
            T1h, T1l, nullptr, nullptr, nullptr, nullptr, nullptr, 128,
            P128, nullptr);

        // h = W1 @ a1 + xs -> H0 (skip store on last layer) ; fused pool -> P128
        __half* outHh = (i == 3) ? nullptr : H0h;
        __half* outHl = (i == 3) ? nullptr : H0l;
        gemm3p<2><<<dim3(128, 1), 256, GSMEM_TOTAL>>>(
            W1h, W1l, 128, T2h, T2l, outHh, outHl, nullptr, nullptr,
            nullptr, nullptr, nullptr, nullptr, nullptr, T4h, T4l, 128,
            nullptr, P128);

        // fold pooled half of next layer's Wd0/Ws into bias vectors
        if (i < 3) {
            bias2_k<<<384, 24>>>(blkWd0 + (size_t)(i + 1) * 256 * 256,
                                 blkWs + (size_t)(i + 1) * 128 * 256,
                                 P128, bWd0, bWs);
        }
    }

    head_kernel<<<B_, 128>>>(P128, actWd, fccW, out);

    (void)in_sizes; (void)n_in; (void)out_size;
}